// round 11
// baseline (speedup 1.0000x reference)
#include <cuda_runtime.h>

#define NN   50000
#define NE   500000
#define HID  128
#define NGR  64
#define REP  32
#define UNB  32    // nodes per update block
#define SBLK 49    // ceil(NN/1024) scan blocks
#define NBN  1563  // ceil(NN/32) node blocks
#define NBC  1954  // ceil(2*NE/512) convert blocks
#define NBS  1954  // ceil(NE/256) scatter blocks

// ---------------- device scratch (no allocations allowed) ----------------
// g_deg, g_sflag, g_gsum, g_gcnt start zero (static init) and are re-zeroed
// by their consumers each call, so every kernel_launch sees identical state.
__device__ __align__(16) float g_pa[NN*HID];        // x @ (Wn Wm_a)
__device__ __align__(16) float g_pb[NN*HID];        // x @ (Wn Wm_b)
__device__ __align__(16) float g_agg[NN*HID];       // normalized message means
__device__ __align__(16) float g_gsum[REP*NGR*HID]; // replicated graph sums
__device__ __align__(16) float g_gcnt[REP*NGR];
__device__ __align__(16) float g_WA[16*HID];        // Wn @ Wm_a
__device__ __align__(16) float g_WB[16*HID];        // Wn @ Wm_b
__device__ __align__(16) float g_WE2[8*HID];        // We @ Wm_c
__device__ __align__(16) float g_WU1[16*HID];       // Wn @ Wu_top
__device__ __align__(16) float g_bconst[HID];       // bn@Wm_a + bn@Wm_b + be@Wm_c + bm
__device__ __align__(16) float g_bup[HID];          // bn@Wu_top + bu
__device__ int  g_row[NE];
__device__ int  g_col[NE];
__device__ int  g_rank[NE];                         // within-destination rank
__device__ int2 g_epack[NE];                        // CSR payload: (src_row, edge_id)
__device__ int  g_deg[NN];
__device__ int  g_ptr[NN+1];
__device__ int  g_bsum[SBLK];
__device__ int  g_sflag[SBLK];
__device__ int  g_batchi[NN];

// ---------------- helpers ----------------
__device__ __forceinline__ void red_f32(float* p, float v) {
    asm volatile("red.global.add.f32 [%0], %1;" :: "l"(p), "f"(v) : "memory");
}
__device__ __forceinline__ unsigned long long splat2(float w) {
    unsigned long long r;
    asm("mov.b64 %0, {%1, %1};" : "=l"(r) : "r"(__float_as_uint(w)));
    return r;
}
__device__ __forceinline__ unsigned long long pack2(float a, float b) {
    unsigned long long r;
    asm("mov.b64 %0, {%1, %2};" : "=l"(r) : "r"(__float_as_uint(a)), "r"(__float_as_uint(b)));
    return r;
}
__device__ __forceinline__ void unpack2(unsigned long long v, float& a, float& b) {
    unsigned lo, hi;
    asm("mov.b64 {%0, %1}, %2;" : "=r"(lo), "=r"(hi) : "l"(v));
    a = __uint_as_float(lo); b = __uint_as_float(hi);
}
__device__ __forceinline__ void fma_f32x2(unsigned long long& d,
                                          unsigned long long a,
                                          unsigned long long b) {
    asm("fma.rn.f32x2 %0, %1, %2, %0;" : "+l"(d) : "l"(a), "l"(b));
}
__device__ __forceinline__ unsigned long long add_f32x2(unsigned long long a,
                                                        unsigned long long b) {
    unsigned long long r;
    asm("add.rn.f32x2 %0, %1, %2;" : "=l"(r) : "l"(a), "l"(b));
    return r;
}

// ---------------- 1: fused weight-fold (blocks 0..56) + convert (rest) ----------------
__global__ __launch_bounds__(512) void k_prepconvert(
        const void* __restrict__ ei, const void* __restrict__ batch,
        const float* __restrict__ Wn, const float* __restrict__ bn,
        const float* __restrict__ We, const float* __restrict__ be,
        const float* __restrict__ Wm, const float* __restrict__ bm,
        const float* __restrict__ Wu, const float* __restrict__ bu) {
    const int t = threadIdx.x;
    const int b = blockIdx.x;

    if (b >= 57) {                     // ---- convert: indices + histogram + rank ----
        int i = (b - 57) * 512 + t;
        const int* ei32 = (const int*)ei;
        bool active = (i < 2*NE);
        int j = (i < NE) ? i : i - NE;
        int hw = active ? ei32[2*j + 1] : 0;
        unsigned m = __ballot_sync(0xffffffffu, active && (hw != 0));
        const bool f64 = (m == 0u);    // int64: all odd words zero
        if (active) {
            int v = f64 ? (int)((const long long*)ei)[i] : ei32[i];
            if (i < NE) {
                g_row[i] = v;
            } else {
                int r = atomicAdd(&g_deg[v], 1);
                g_col[i - NE]  = v;
                g_rank[i - NE] = r;
            }
        }
        if (i < NN) {
            g_batchi[i] = f64 ? (int)((const long long*)batch)[i] : ((const int*)batch)[i];
        }
        return;
    }

    // ---- prep: split-K weight folds ----
    __shared__ float swl[HID];
    __shared__ float sred[4][HID];
    __shared__ float sred4[4][4][HID];
    __shared__ float sbn[HID], sbe[HID];
    const int c = t & 127;
    const int q = t >> 7;

    if (b < 56) {
        const float* Wl;
        const float* Wr;
        float* out;
        int orow;
        if (b < 48) {
            int grp = b >> 4;
            orow = b & 15;
            Wl = Wn + orow*HID;
            if      (grp == 0) { Wr = Wm;           out = g_WA;  }
            else if (grp == 1) { Wr = Wm + HID*HID; out = g_WB;  }
            else               { Wr = Wu;           out = g_WU1; }
        } else {
            orow = b - 48;
            Wl = We + orow*HID;
            Wr = Wm + 2*HID*HID;
            out = g_WE2;
        }
        if (t < HID) swl[t] = Wl[t];
        __syncthreads();
        float a0 = 0.f, a1 = 0.f;
        const int k0 = 32*q;
        #pragma unroll
        for (int kk = 0; kk < 32; kk += 2) {
            a0 += swl[k0+kk]   * Wr[(k0+kk)*HID + c];
            a1 += swl[k0+kk+1] * Wr[(k0+kk+1)*HID + c];
        }
        sred[q][c] = a0 + a1;
        __syncthreads();
        if (q == 0)
            out[orow*HID + c] = (sred[0][c] + sred[1][c]) + (sred[2][c] + sred[3][c]);
    } else {
        if (t < HID) { sbn[t] = bn[t]; sbe[t] = be[t]; }
        __syncthreads();
        float p0 = 0.f, p1 = 0.f, p2 = 0.f, p3 = 0.f;
        const int k0 = 32*q;
        #pragma unroll
        for (int kk = 0; kk < 32; kk++) {
            int k = k0 + kk;
            float bnk = sbn[k];
            p0 += bnk    * Wm[k*HID + c];
            p1 += bnk    * Wm[(HID + k)*HID + c];
            p2 += sbe[k] * Wm[(2*HID + k)*HID + c];
            p3 += bnk    * Wu[k*HID + c];
        }
        sred4[q][0][c] = p0; sred4[q][1][c] = p1;
        sred4[q][2][c] = p2; sred4[q][3][c] = p3;
        __syncthreads();
        if (q == 0) {
            float b0 = sred4[0][0][c]+sred4[1][0][c]+sred4[2][0][c]+sred4[3][0][c];
            float b1 = sred4[0][1][c]+sred4[1][1][c]+sred4[2][1][c]+sred4[3][1][c];
            float b2 = sred4[0][2][c]+sred4[1][2][c]+sred4[2][2][c]+sred4[3][2][c];
            float u0 = sred4[0][3][c]+sred4[1][3][c]+sred4[2][3][c]+sred4[3][3][c];
            g_bconst[c] = bm[c] + b0 + b1 + b2;
            g_bup[c]    = bu[c] + u0;
        }
    }
}

// ---------------- 2: fused exclusive scan (decoupled lookback), clears g_deg ----------------
__global__ __launch_bounds__(1024) void k_scan() {
    __shared__ int swsum[32];
    __shared__ int soff;
    int t = threadIdx.x, b = blockIdx.x;
    int idx = b * 1024 + t;
    int lane = t & 31, warp = t >> 5;
    int d = (idx < NN) ? g_deg[idx] : 0;
    if (idx < NN) g_deg[idx] = 0;            // consume-and-clear for next call

    int v = d;
    #pragma unroll
    for (int o = 1; o < 32; o <<= 1) {
        int u = __shfl_up_sync(0xffffffffu, v, o);
        if (lane >= o) v += u;
    }
    if (lane == 31) swsum[warp] = v;
    __syncthreads();
    if (warp == 0) {
        int s = swsum[lane];
        #pragma unroll
        for (int o = 1; o < 32; o <<= 1) {
            int u = __shfl_up_sync(0xffffffffu, s, o);
            if (lane >= o) s += u;
        }
        swsum[lane] = s;
    }
    __syncthreads();
    int incl = v + ((warp > 0) ? swsum[warp - 1] : 0);

    if (t == 1023) {                          // publish block total
        g_bsum[b] = incl;
        __threadfence();
        atomicExch(&g_sflag[b], 1);
    }
    if (t < 32) {                             // lookback over predecessors
        int acc = 0;
        for (int j = t; j < b; j += 32) {
            while (atomicAdd(&g_sflag[j], 0) == 0) {}
            acc += atomicAdd(&g_bsum[j], 0);
        }
        #pragma unroll
        for (int o = 16; o > 0; o >>= 1) acc += __shfl_down_sync(0xffffffffu, acc, o);
        if (t == 0) soff = acc;
    }
    __syncthreads();
    if (idx < NN) g_ptr[idx] = (incl - d) + soff;
    if (b == 0 && t == 0) g_ptr[NN] = NE;     // degree sum is NE by construction
}

// ---------------- 3: fused node projections (blocks 0..NBN-1) + scatter (rest) ----------------
__global__ __launch_bounds__(256) void k_scatternode(const float* __restrict__ x) {
    const int t = threadIdx.x;
    const int b = blockIdx.x;

    if (b >= NBN) {                    // ---- scatter (pure stores) + clear sflag ----
        int i = (b - NBN) * 256 + t;
        if (i < NE) {
            int c = g_col[i];
            g_epack[g_ptr[c] + g_rank[i]] = make_int2(g_row[i], i);
        }
        if (i < SBLK) g_sflag[i] = 0;  // consume-and-clear for next call
        return;
    }

    // ---- node: pa/pb via channel-per-thread, broadcast LDS, f32x2 ----
    __shared__ __align__(16) float sxT[16][36];   // [i][n], 144B rows
    const int n0 = b * 32;
    #pragma unroll
    for (int r = 0; r < 2; r++) {
        int f = t + 256*r;             // 512 elements = 32 nodes x 16 feats
        int n = f >> 4, i = f & 15;
        int node = n0 + n;
        sxT[i][n] = (node < NN) ? x[(long long)node*16 + i] : 0.f;
    }
    __syncthreads();

    const int ch  = t & 127;
    const float* W   = (t >= 128) ? g_WB : g_WA;
    float*       OUT = (t >= 128) ? g_pb : g_pa;

    unsigned long long acc2[16];
    #pragma unroll
    for (int p = 0; p < 16; p++) acc2[p] = 0ULL;

    #pragma unroll
    for (int i = 0; i < 16; i++) {
        unsigned long long w2 = splat2(W[i*HID + ch]);
        const ulonglong2* srow = (const ulonglong2*)&sxT[i][0];
        #pragma unroll
        for (int qq = 0; qq < 8; qq++) {
            ulonglong2 a = srow[qq];   // broadcast (all lanes same addr)
            fma_f32x2(acc2[2*qq],   a.x, w2);
            fma_f32x2(acc2[2*qq+1], a.y, w2);
        }
    }
    #pragma unroll
    for (int p = 0; p < 16; p++) {
        float v0, v1;
        unpack2(acc2[p], v0, v1);
        int na = n0 + 2*p, nb2 = n0 + 2*p + 1;
        if (na  < NN) OUT[(long long)na *HID + ch] = v0;   // coalesced across ch
        if (nb2 < NN) OUT[(long long)nb2*HID + ch] = v1;
    }
}

// ---------------- 4: CSR aggregation — regs capped for 4 blocks/SM ----------------
__global__ __launch_bounds__(256, 4) void k_agg(const float* __restrict__ ea) {
    __shared__ float4 sbc[32];
    int t = threadIdx.x;
    int warp = t >> 5, lane = t & 31;

    unsigned long long wx[8], wy[8];   // WE2[j][4*lane..4*lane+3] per lane
    #pragma unroll
    for (int j = 0; j < 8; j++) {
        ulonglong2 w = ((const ulonglong2*)g_WE2)[j*32 + lane];
        wx[j] = w.x; wy[j] = w.y;
    }
    if (t < 32) sbc[t] = ((const float4*)g_bconst)[t];
    __syncthreads();

    int node = blockIdx.x * 8 + warp;
    if (node >= NN) return;
    int beg = g_ptr[node];
    int end = g_ptr[node + 1];

    float4 pbv = ((const float4*)g_pb)[node*32 + lane];
    float4 bc  = sbc[lane];
    unsigned long long bx0 = pack2(pbv.x + bc.x, pbv.y + bc.y);
    unsigned long long bx1 = pack2(pbv.z + bc.z, pbv.w + bc.w);

    float4 acc = {0.f, 0.f, 0.f, 0.f};
    // 1-ahead pipeline: epack + pa gather + ea (prefetch only one edge of state)
    int2 e = {0, 0};
    ulonglong2 pav = {0ULL, 0ULL};
    float4 A = {0,0,0,0}, B = {0,0,0,0};
    if (beg < end) {
        e = g_epack[beg];
        pav = ((const ulonglong2*)g_pa)[e.x*32 + lane];
        const float4* eap = (const float4*)(ea + (long long)e.y*8);
        A = eap[0]; B = eap[1];
    }
    for (int p = beg; p < end; p++) {
        ulonglong2 pc = pav;
        float4 Ac = A, Bc = B;
        if (p + 1 < end) {
            e = g_epack[p + 1];
            pav = ((const ulonglong2*)g_pa)[e.x*32 + lane];
            const float4* eap = (const float4*)(ea + (long long)e.y*8);
            A = eap[0]; B = eap[1];
        }
        unsigned long long m0 = add_f32x2(pc.x, bx0);
        unsigned long long m1 = add_f32x2(pc.y, bx1);
        float ej[8] = {Ac.x, Ac.y, Ac.z, Ac.w, Bc.x, Bc.y, Bc.z, Bc.w};
        #pragma unroll
        for (int j = 0; j < 8; j++) {
            unsigned long long ej2 = splat2(ej[j]);
            fma_f32x2(m0, ej2, wx[j]);
            fma_f32x2(m1, ej2, wy[j]);
        }
        float f0, f1, f2, f3;
        unpack2(m0, f0, f1);
        unpack2(m1, f2, f3);
        acc.x += fmaxf(f0, 0.f);
        acc.y += fmaxf(f1, 0.f);
        acc.z += fmaxf(f2, 0.f);
        acc.w += fmaxf(f3, 0.f);
    }
    float inv = 1.f / fmaxf((float)(end - beg), 1.f);
    acc.x *= inv; acc.y *= inv; acc.z *= inv; acc.w *= inv;
    ((float4*)g_agg)[node*32 + lane] = acc;
}

// ---------------- 5: node update + graph pooling ----------------
__global__ __launch_bounds__(128) void k_update(const float* __restrict__ x,
                                                const float* __restrict__ Wu) {
    __shared__ __align__(16) float saggT[HID][UNB + 4];
    __shared__ __align__(16) float sxT[16][UNB + 4];
    __shared__ int sbatch[UNB];
    int t  = threadIdx.x;                   // thread = channel c
    int n0 = blockIdx.x * UNB;

    if (t < UNB) {
        int node = n0 + t;
        sbatch[t] = (node < NN) ? g_batchi[node] : 0;
    }
    for (int n = 0; n < UNB; n++) {
        int node = n0 + n;
        saggT[t][n] = (node < NN) ? g_agg[node*HID + t] : 0.f;
    }
    for (int idx = t; idx < 16*UNB; idx += 128) {
        int n = idx & 31, i = idx >> 5;
        int node = n0 + n;
        sxT[i][n] = (node < NN) ? x[node*16 + i] : 0.f;
    }
    __syncthreads();

    const int c = t;
    unsigned long long acc2[UNB/2];
    #pragma unroll
    for (int p = 0; p < UNB/2; p++) acc2[p] = 0ULL;

    #pragma unroll
    for (int i = 0; i < 16; i++) {
        unsigned long long w2 = splat2(g_WU1[i*HID + c]);
        const ulonglong2* srow = (const ulonglong2*)&sxT[i][0];
        #pragma unroll
        for (int q = 0; q < UNB/4; q++) {
            ulonglong2 a = srow[q];
            fma_f32x2(acc2[2*q],   a.x, w2);
            fma_f32x2(acc2[2*q+1], a.y, w2);
        }
    }
    for (int k = 0; k < HID; k++) {
        unsigned long long w2 = splat2(Wu[(HID + k)*HID + c]);   // Wu_bot
        const ulonglong2* srow = (const ulonglong2*)&saggT[k][0];
        #pragma unroll
        for (int q = 0; q < UNB/4; q++) {
            ulonglong2 a = srow[q];
            fma_f32x2(acc2[2*q],   a.x, w2);
            fma_f32x2(acc2[2*q+1], a.y, w2);
        }
    }

    float bupv = g_bup[c];
    int   rep  = blockIdx.x & (REP - 1);
    float* gsbase = &g_gsum[rep*NGR*HID];
    int   cur = sbatch[0];
    float sum = 0.f;
    #pragma unroll
    for (int p = 0; p < UNB/2; p++) {
        float hv[2];
        unpack2(acc2[p], hv[0], hv[1]);
        #pragma unroll
        for (int q = 0; q < 2; q++) {
            int n = 2*p + q;
            int node = n0 + n;
            if (node < NN) {
                float h = fmaxf(hv[q] + bupv, 0.f);
                int b = sbatch[n];
                if (b != cur) {
                    red_f32(gsbase + cur*HID + c, sum);
                    cur = b; sum = 0.f;
                }
                sum += h;
            }
        }
    }
    red_f32(gsbase + cur*HID + c, sum);

    if (t < UNB) {
        int node = n0 + t;
        if (node < NN) red_f32(&g_gcnt[rep*NGR + sbatch[t]], 1.0f);
    }
}

// ---------------- 6: readout MLP, clears g_gsum/g_gcnt ----------------
__global__ __launch_bounds__(128) void k_final(const float* __restrict__ Wr1,
                                               const float* __restrict__ br1,
                                               const float* __restrict__ Wr2,
                                               const float* __restrict__ br2,
                                               float* __restrict__ out) {
    __shared__ float sg[HID];
    __shared__ float sred[4];
    int g = blockIdx.x, t = threadIdx.x;
    float s = 0.f;
    for (int r = 0; r < REP; r++) s += g_gsum[r*NGR*HID + g*HID + t];
    float gc = 0.f;
    for (int r = 0; r < REP; r++) gc += g_gcnt[r*NGR + g];
    sg[t] = s / fmaxf(gc, 1.f);
    __syncthreads();
    // consume-and-clear (this block owns graph g's slots)
    for (int r = 0; r < REP; r++) g_gsum[r*NGR*HID + g*HID + t] = 0.f;
    if (t == 0) for (int r = 0; r < REP; r++) g_gcnt[r*NGR + g] = 0.f;

    float acc = br1[t];
    for (int k = 0; k < HID; k++) acc += sg[k] * Wr1[k*HID + t];
    acc = fmaxf(acc, 0.f);
    float v = acc * Wr2[t];
    #pragma unroll
    for (int o = 16; o > 0; o >>= 1) v += __shfl_down_sync(0xffffffffu, v, o);
    if ((t & 31) == 0) sred[t >> 5] = v;
    __syncthreads();
    if (t == 0) out[g] = sred[0] + sred[1] + sred[2] + sred[3] + br2[0];
}

// ---------------- launch ----------------
extern "C" void kernel_launch(void* const* d_in, const int* in_sizes, int n_in,
                              void* d_out, int out_size) {
    const float* x     = (const float*)d_in[0];
    const float* ea    = (const float*)d_in[1];
    const void*  ei    = d_in[2];
    const void*  batch = d_in[3];
    const float* Wn  = (const float*)d_in[4];
    const float* bn  = (const float*)d_in[5];
    const float* We  = (const float*)d_in[6];
    const float* be  = (const float*)d_in[7];
    const float* Wm  = (const float*)d_in[8];
    const float* bm  = (const float*)d_in[9];
    const float* Wu  = (const float*)d_in[10];
    const float* bu  = (const float*)d_in[11];
    const float* Wr1 = (const float*)d_in[12];
    const float* br1 = (const float*)d_in[13];
    const float* Wr2 = (const float*)d_in[14];
    const float* br2 = (const float*)d_in[15];
    float* out = (float*)d_out;

    k_prepconvert <<<57 + NBC, 512>>>(ei, batch, Wn, bn, We, be, Wm, bm, Wu, bu);
    k_scan        <<<SBLK, 1024>>>();
    k_scatternode <<<NBN + NBS, 256>>>(x);
    k_agg         <<<(NN + 7)/8, 256>>>(ea);     // launch #4 -> profiled
    k_update      <<<(NN + UNB - 1)/UNB, 128>>>(x, Wu);
    k_final       <<<NGR, 128>>>(Wr1, br1, Wr2, br2, out);
}

// round 12
// speedup vs baseline: 1.2711x; 1.2711x over previous
#include <cuda_runtime.h>

#define NN   50000
#define NE   500000
#define HID  128
#define NGR  64
#define REP  32
#define UNB  32    // nodes per update block
#define SBLK 49    // ceil(NN/1024) scan blocks
#define NBN  1563  // ceil(NN/32) node blocks
#define NBC  1954  // ceil(2*NE/512) convert blocks
#define NBS  1954  // ceil(NE/256) scatter blocks

// ---------------- device scratch (no allocations allowed) ----------------
// g_deg, g_sflag, g_gsum, g_gcnt start zero (static init) and are re-zeroed
// by their consumers each call, so every kernel_launch sees identical state.
__device__ __align__(16) float g_pa[NN*HID];        // x @ (Wn Wm_a)
__device__ __align__(16) float g_pb[NN*HID];        // x @ (Wn Wm_b)
__device__ __align__(16) float g_agg[NN*HID];       // normalized message means
__device__ __align__(16) float g_gsum[REP*NGR*HID]; // replicated graph sums
__device__ __align__(16) float g_gcnt[REP*NGR];
__device__ __align__(16) float g_WA[16*HID];        // Wn @ Wm_a
__device__ __align__(16) float g_WB[16*HID];        // Wn @ Wm_b
__device__ __align__(16) float g_WE2[8*HID];        // We @ Wm_c
__device__ __align__(16) float g_WU1[16*HID];       // Wn @ Wu_top
__device__ __align__(16) float g_bconst[HID];       // bn@Wm_a + bn@Wm_b + be@Wm_c + bm
__device__ __align__(16) float g_bup[HID];          // bn@Wu_top + bu
__device__ int  g_row[NE];
__device__ int  g_col[NE];
__device__ int  g_rank[NE];                         // within-destination rank
__device__ int2 g_epack[NE];                        // CSR payload: (src_row, edge_id)
__device__ int  g_deg[NN];
__device__ int  g_ptr[NN+1];
__device__ int  g_bsum[SBLK];
__device__ int  g_sflag[SBLK];
__device__ int  g_batchi[NN];

// ---------------- helpers ----------------
__device__ __forceinline__ void red_f32(float* p, float v) {
    asm volatile("red.global.add.f32 [%0], %1;" :: "l"(p), "f"(v) : "memory");
}
__device__ __forceinline__ unsigned long long splat2(float w) {
    unsigned long long r;
    asm("mov.b64 %0, {%1, %1};" : "=l"(r) : "r"(__float_as_uint(w)));
    return r;
}
__device__ __forceinline__ unsigned long long pack2(float a, float b) {
    unsigned long long r;
    asm("mov.b64 %0, {%1, %2};" : "=l"(r) : "r"(__float_as_uint(a)), "r"(__float_as_uint(b)));
    return r;
}
__device__ __forceinline__ void unpack2(unsigned long long v, float& a, float& b) {
    unsigned lo, hi;
    asm("mov.b64 {%0, %1}, %2;" : "=r"(lo), "=r"(hi) : "l"(v));
    a = __uint_as_float(lo); b = __uint_as_float(hi);
}
__device__ __forceinline__ void fma_f32x2(unsigned long long& d,
                                          unsigned long long a,
                                          unsigned long long b) {
    asm("fma.rn.f32x2 %0, %1, %2, %0;" : "+l"(d) : "l"(a), "l"(b));
}
__device__ __forceinline__ unsigned long long add_f32x2(unsigned long long a,
                                                        unsigned long long b) {
    unsigned long long r;
    asm("add.rn.f32x2 %0, %1, %2;" : "=l"(r) : "l"(a), "l"(b));
    return r;
}

// ---------------- 1: fused weight-fold (blocks 0..56) + convert (rest) ----------------
__global__ __launch_bounds__(512) void k_prepconvert(
        const void* __restrict__ ei, const void* __restrict__ batch,
        const float* __restrict__ Wn, const float* __restrict__ bn,
        const float* __restrict__ We, const float* __restrict__ be,
        const float* __restrict__ Wm, const float* __restrict__ bm,
        const float* __restrict__ Wu, const float* __restrict__ bu) {
    const int t = threadIdx.x;
    const int b = blockIdx.x;

    if (b >= 57) {                     // ---- convert: indices + histogram + rank ----
        int i = (b - 57) * 512 + t;
        const int* ei32 = (const int*)ei;
        bool active = (i < 2*NE);
        int j = (i < NE) ? i : i - NE;
        int hw = active ? ei32[2*j + 1] : 0;
        unsigned m = __ballot_sync(0xffffffffu, active && (hw != 0));
        const bool f64 = (m == 0u);    // int64: all odd words zero
        if (active) {
            int v = f64 ? (int)((const long long*)ei)[i] : ei32[i];
            if (i < NE) {
                g_row[i] = v;
            } else {
                int r = atomicAdd(&g_deg[v], 1);
                g_col[i - NE]  = v;
                g_rank[i - NE] = r;
            }
        }
        if (i < NN) {
            g_batchi[i] = f64 ? (int)((const long long*)batch)[i] : ((const int*)batch)[i];
        }
        return;
    }

    // ---- prep: split-K weight folds ----
    __shared__ float swl[HID];
    __shared__ float sred[4][HID];
    __shared__ float sred4[4][4][HID];
    __shared__ float sbn[HID], sbe[HID];
    const int c = t & 127;
    const int q = t >> 7;

    if (b < 56) {
        const float* Wl;
        const float* Wr;
        float* out;
        int orow;
        if (b < 48) {
            int grp = b >> 4;
            orow = b & 15;
            Wl = Wn + orow*HID;
            if      (grp == 0) { Wr = Wm;           out = g_WA;  }
            else if (grp == 1) { Wr = Wm + HID*HID; out = g_WB;  }
            else               { Wr = Wu;           out = g_WU1; }
        } else {
            orow = b - 48;
            Wl = We + orow*HID;
            Wr = Wm + 2*HID*HID;
            out = g_WE2;
        }
        if (t < HID) swl[t] = Wl[t];
        __syncthreads();
        float a0 = 0.f, a1 = 0.f;
        const int k0 = 32*q;
        #pragma unroll
        for (int kk = 0; kk < 32; kk += 2) {
            a0 += swl[k0+kk]   * Wr[(k0+kk)*HID + c];
            a1 += swl[k0+kk+1] * Wr[(k0+kk+1)*HID + c];
        }
        sred[q][c] = a0 + a1;
        __syncthreads();
        if (q == 0)
            out[orow*HID + c] = (sred[0][c] + sred[1][c]) + (sred[2][c] + sred[3][c]);
    } else {
        if (t < HID) { sbn[t] = bn[t]; sbe[t] = be[t]; }
        __syncthreads();
        float p0 = 0.f, p1 = 0.f, p2 = 0.f, p3 = 0.f;
        const int k0 = 32*q;
        #pragma unroll
        for (int kk = 0; kk < 32; kk++) {
            int k = k0 + kk;
            float bnk = sbn[k];
            p0 += bnk    * Wm[k*HID + c];
            p1 += bnk    * Wm[(HID + k)*HID + c];
            p2 += sbe[k] * Wm[(2*HID + k)*HID + c];
            p3 += bnk    * Wu[k*HID + c];
        }
        sred4[q][0][c] = p0; sred4[q][1][c] = p1;
        sred4[q][2][c] = p2; sred4[q][3][c] = p3;
        __syncthreads();
        if (q == 0) {
            float b0 = sred4[0][0][c]+sred4[1][0][c]+sred4[2][0][c]+sred4[3][0][c];
            float b1 = sred4[0][1][c]+sred4[1][1][c]+sred4[2][1][c]+sred4[3][1][c];
            float b2 = sred4[0][2][c]+sred4[1][2][c]+sred4[2][2][c]+sred4[3][2][c];
            float u0 = sred4[0][3][c]+sred4[1][3][c]+sred4[2][3][c]+sred4[3][3][c];
            g_bconst[c] = bm[c] + b0 + b1 + b2;
            g_bup[c]    = bu[c] + u0;
        }
    }
}

// ---------------- 2: fused exclusive scan (decoupled lookback), clears g_deg ----------------
__global__ __launch_bounds__(1024) void k_scan() {
    __shared__ int swsum[32];
    __shared__ int soff;
    int t = threadIdx.x, b = blockIdx.x;
    int idx = b * 1024 + t;
    int lane = t & 31, warp = t >> 5;
    int d = (idx < NN) ? g_deg[idx] : 0;
    if (idx < NN) g_deg[idx] = 0;            // consume-and-clear for next call

    int v = d;
    #pragma unroll
    for (int o = 1; o < 32; o <<= 1) {
        int u = __shfl_up_sync(0xffffffffu, v, o);
        if (lane >= o) v += u;
    }
    if (lane == 31) swsum[warp] = v;
    __syncthreads();
    if (warp == 0) {
        int s = swsum[lane];
        #pragma unroll
        for (int o = 1; o < 32; o <<= 1) {
            int u = __shfl_up_sync(0xffffffffu, s, o);
            if (lane >= o) s += u;
        }
        swsum[lane] = s;
    }
    __syncthreads();
    int incl = v + ((warp > 0) ? swsum[warp - 1] : 0);

    if (t == 1023) {                          // publish block total
        g_bsum[b] = incl;
        __threadfence();
        atomicExch(&g_sflag[b], 1);
    }
    if (t < 32) {                             // lookback over predecessors
        int acc = 0;
        for (int j = t; j < b; j += 32) {
            while (atomicAdd(&g_sflag[j], 0) == 0) {}
            acc += atomicAdd(&g_bsum[j], 0);
        }
        #pragma unroll
        for (int o = 16; o > 0; o >>= 1) acc += __shfl_down_sync(0xffffffffu, acc, o);
        if (t == 0) soff = acc;
    }
    __syncthreads();
    if (idx < NN) g_ptr[idx] = (incl - d) + soff;
    if (b == 0 && t == 0) g_ptr[NN] = NE;     // degree sum is NE by construction
}

// ---------------- 3: fused node projections (blocks 0..NBN-1) + scatter (rest) ----------------
__global__ __launch_bounds__(256) void k_scatternode(const float* __restrict__ x) {
    const int t = threadIdx.x;
    const int b = blockIdx.x;

    if (b >= NBN) {                    // ---- scatter (pure stores) + clear sflag ----
        int i = (b - NBN) * 256 + t;
        if (i < NE) {
            int c = g_col[i];
            g_epack[g_ptr[c] + g_rank[i]] = make_int2(g_row[i], i);
        }
        if (i < SBLK) g_sflag[i] = 0;  // consume-and-clear for next call
        return;
    }

    // ---- node: pa/pb via channel-per-thread, broadcast LDS, f32x2 ----
    __shared__ __align__(16) float sxT[16][36];   // [i][n], 144B rows
    const int n0 = b * 32;
    #pragma unroll
    for (int r = 0; r < 2; r++) {
        int f = t + 256*r;             // 512 elements = 32 nodes x 16 feats
        int n = f >> 4, i = f & 15;
        int node = n0 + n;
        sxT[i][n] = (node < NN) ? x[(long long)node*16 + i] : 0.f;
    }
    __syncthreads();

    const int ch  = t & 127;
    const float* W   = (t >= 128) ? g_WB : g_WA;
    float*       OUT = (t >= 128) ? g_pb : g_pa;

    unsigned long long acc2[16];
    #pragma unroll
    for (int p = 0; p < 16; p++) acc2[p] = 0ULL;

    #pragma unroll
    for (int i = 0; i < 16; i++) {
        unsigned long long w2 = splat2(W[i*HID + ch]);
        const ulonglong2* srow = (const ulonglong2*)&sxT[i][0];
        #pragma unroll
        for (int qq = 0; qq < 8; qq++) {
            ulonglong2 a = srow[qq];   // broadcast (all lanes same addr)
            fma_f32x2(acc2[2*qq],   a.x, w2);
            fma_f32x2(acc2[2*qq+1], a.y, w2);
        }
    }
    #pragma unroll
    for (int p = 0; p < 16; p++) {
        float v0, v1;
        unpack2(acc2[p], v0, v1);
        int na = n0 + 2*p, nb2 = n0 + 2*p + 1;
        if (na  < NN) OUT[(long long)na *HID + ch] = v0;   // coalesced across ch
        if (nb2 < NN) OUT[(long long)nb2*HID + ch] = v1;
    }
}

// ---------------- 4: CSR aggregation — R10 body, 128-thr blocks for occupancy ----------------
__global__ __launch_bounds__(128) void k_agg(const float* __restrict__ ea) {
    __shared__ float4 sbc[32];
    int t = threadIdx.x;
    int warp = t >> 5, lane = t & 31;

    unsigned long long wx[8], wy[8];   // WE2[j][4*lane..4*lane+3] per lane
    #pragma unroll
    for (int j = 0; j < 8; j++) {
        ulonglong2 w = ((const ulonglong2*)g_WE2)[j*32 + lane];
        wx[j] = w.x; wy[j] = w.y;
    }
    if (t < 32) sbc[t] = ((const float4*)g_bconst)[t];
    __syncthreads();

    int node = blockIdx.x * 4 + warp;
    if (node >= NN) return;
    int beg = g_ptr[node];
    int end = g_ptr[node + 1];

    float4 pbv = ((const float4*)g_pb)[node*32 + lane];
    float4 bc  = sbc[lane];
    unsigned long long bx0 = pack2(pbv.x + bc.x, pbv.y + bc.y);
    unsigned long long bx1 = pack2(pbv.z + bc.z, pbv.w + bc.w);

    float4 acc = {0.f, 0.f, 0.f, 0.f};
    int2 e1 = {0,0}, e2 = {0,0};
    ulonglong2 pav = {0ULL, 0ULL};
    float4 A = {0,0,0,0}, B = {0,0,0,0};
    if (beg < end)     e1 = g_epack[beg];
    if (beg + 1 < end) e2 = g_epack[beg + 1];
    if (beg < end) {
        pav = ((const ulonglong2*)g_pa)[e1.x*32 + lane];
        const float4* eap = (const float4*)(ea + (long long)e1.y*8);
        A = eap[0]; B = eap[1];
    }
    for (int p = beg; p < end; p++) {
        ulonglong2 pc = pav;
        float4 Ac = A, Bc = B;
        e1 = e2;
        if (p + 2 < end) e2 = g_epack[p + 2];
        if (p + 1 < end) {
            pav = ((const ulonglong2*)g_pa)[e1.x*32 + lane];
            const float4* eap = (const float4*)(ea + (long long)e1.y*8);
            A = eap[0]; B = eap[1];
        }
        unsigned long long m0 = add_f32x2(pc.x, bx0);
        unsigned long long m1 = add_f32x2(pc.y, bx1);
        float ej[8] = {Ac.x, Ac.y, Ac.z, Ac.w, Bc.x, Bc.y, Bc.z, Bc.w};
        #pragma unroll
        for (int j = 0; j < 8; j++) {
            unsigned long long ej2 = splat2(ej[j]);
            fma_f32x2(m0, ej2, wx[j]);
            fma_f32x2(m1, ej2, wy[j]);
        }
        float f0, f1, f2, f3;
        unpack2(m0, f0, f1);
        unpack2(m1, f2, f3);
        acc.x += fmaxf(f0, 0.f);
        acc.y += fmaxf(f1, 0.f);
        acc.z += fmaxf(f2, 0.f);
        acc.w += fmaxf(f3, 0.f);
    }
    float inv = 1.f / fmaxf((float)(end - beg), 1.f);
    acc.x *= inv; acc.y *= inv; acc.z *= inv; acc.w *= inv;
    ((float4*)g_agg)[node*32 + lane] = acc;
}

// ---------------- 5: node update + graph pooling ----------------
__global__ __launch_bounds__(128) void k_update(const float* __restrict__ x,
                                                const float* __restrict__ Wu) {
    __shared__ __align__(16) float saggT[HID][UNB + 4];
    __shared__ __align__(16) float sxT[16][UNB + 4];
    __shared__ int sbatch[UNB];
    int t  = threadIdx.x;                   // thread = channel c
    int n0 = blockIdx.x * UNB;

    if (t < UNB) {
        int node = n0 + t;
        sbatch[t] = (node < NN) ? g_batchi[node] : 0;
    }
    for (int n = 0; n < UNB; n++) {
        int node = n0 + n;
        saggT[t][n] = (node < NN) ? g_agg[node*HID + t] : 0.f;
    }
    for (int idx = t; idx < 16*UNB; idx += 128) {
        int n = idx & 31, i = idx >> 5;
        int node = n0 + n;
        sxT[i][n] = (node < NN) ? x[node*16 + i] : 0.f;
    }
    __syncthreads();

    const int c = t;
    unsigned long long acc2[UNB/2];
    #pragma unroll
    for (int p = 0; p < UNB/2; p++) acc2[p] = 0ULL;

    #pragma unroll
    for (int i = 0; i < 16; i++) {
        unsigned long long w2 = splat2(g_WU1[i*HID + c]);
        const ulonglong2* srow = (const ulonglong2*)&sxT[i][0];
        #pragma unroll
        for (int q = 0; q < UNB/4; q++) {
            ulonglong2 a = srow[q];
            fma_f32x2(acc2[2*q],   a.x, w2);
            fma_f32x2(acc2[2*q+1], a.y, w2);
        }
    }
    for (int k = 0; k < HID; k++) {
        unsigned long long w2 = splat2(Wu[(HID + k)*HID + c]);   // Wu_bot
        const ulonglong2* srow = (const ulonglong2*)&saggT[k][0];
        #pragma unroll
        for (int q = 0; q < UNB/4; q++) {
            ulonglong2 a = srow[q];
            fma_f32x2(acc2[2*q],   a.x, w2);
            fma_f32x2(acc2[2*q+1], a.y, w2);
        }
    }

    float bupv = g_bup[c];
    int   rep  = blockIdx.x & (REP - 1);
    float* gsbase = &g_gsum[rep*NGR*HID];
    int   cur = sbatch[0];
    float sum = 0.f;
    #pragma unroll
    for (int p = 0; p < UNB/2; p++) {
        float hv[2];
        unpack2(acc2[p], hv[0], hv[1]);
        #pragma unroll
        for (int q = 0; q < 2; q++) {
            int n = 2*p + q;
            int node = n0 + n;
            if (node < NN) {
                float h = fmaxf(hv[q] + bupv, 0.f);
                int b = sbatch[n];
                if (b != cur) {
                    red_f32(gsbase + cur*HID + c, sum);
                    cur = b; sum = 0.f;
                }
                sum += h;
            }
        }
    }
    red_f32(gsbase + cur*HID + c, sum);

    if (t < UNB) {
        int node = n0 + t;
        if (node < NN) red_f32(&g_gcnt[rep*NGR + sbatch[t]], 1.0f);
    }
}

// ---------------- 6: readout MLP, clears g_gsum/g_gcnt ----------------
__global__ __launch_bounds__(128) void k_final(const float* __restrict__ Wr1,
                                               const float* __restrict__ br1,
                                               const float* __restrict__ Wr2,
                                               const float* __restrict__ br2,
                                               float* __restrict__ out) {
    __shared__ float sg[HID];
    __shared__ float sred[4];
    int g = blockIdx.x, t = threadIdx.x;
    float s = 0.f;
    for (int r = 0; r < REP; r++) s += g_gsum[r*NGR*HID + g*HID + t];
    float gc = 0.f;
    for (int r = 0; r < REP; r++) gc += g_gcnt[r*NGR + g];
    sg[t] = s / fmaxf(gc, 1.f);
    __syncthreads();
    // consume-and-clear (this block owns graph g's slots)
    for (int r = 0; r < REP; r++) g_gsum[r*NGR*HID + g*HID + t] = 0.f;
    if (t == 0) for (int r = 0; r < REP; r++) g_gcnt[r*NGR + g] = 0.f;

    float acc = br1[t];
    for (int k = 0; k < HID; k++) acc += sg[k] * Wr1[k*HID + t];
    acc = fmaxf(acc, 0.f);
    float v = acc * Wr2[t];
    #pragma unroll
    for (int o = 16; o > 0; o >>= 1) v += __shfl_down_sync(0xffffffffu, v, o);
    if ((t & 31) == 0) sred[t >> 5] = v;
    __syncthreads();
    if (t == 0) out[g] = sred[0] + sred[1] + sred[2] + sred[3] + br2[0];
}

// ---------------- launch ----------------
extern "C" void kernel_launch(void* const* d_in, const int* in_sizes, int n_in,
                              void* d_out, int out_size) {
    const float* x     = (const float*)d_in[0];
    const float* ea    = (const float*)d_in[1];
    const void*  ei    = d_in[2];
    const void*  batch = d_in[3];
    const float* Wn  = (const float*)d_in[4];
    const float* bn  = (const float*)d_in[5];
    const float* We  = (const float*)d_in[6];
    const float* be  = (const float*)d_in[7];
    const float* Wm  = (const float*)d_in[8];
    const float* bm  = (const float*)d_in[9];
    const float* Wu  = (const float*)d_in[10];
    const float* bu  = (const float*)d_in[11];
    const float* Wr1 = (const float*)d_in[12];
    const float* br1 = (const float*)d_in[13];
    const float* Wr2 = (const float*)d_in[14];
    const float* br2 = (const float*)d_in[15];
    float* out = (float*)d_out;

    k_prepconvert <<<57 + NBC, 512>>>(ei, batch, Wn, bn, We, be, Wm, bm, Wu, bu);
    k_scan        <<<SBLK, 1024>>>();
    k_scatternode <<<NBN + NBS, 256>>>(x);
    k_agg         <<<(NN + 3)/4, 128>>>(ea);     // launch #4 -> profiled
    k_update      <<<(NN + UNB - 1)/UNB, 128>>>(x, Wu);
    k_final       <<<NGR, 128>>>(Wr1, br1, Wr2, br2, out);
}

// round 13
// speedup vs baseline: 1.3208x; 1.0391x over previous
#include <cuda_runtime.h>

#define NN   50000
#define NE   500000
#define HID  128
#define NGR  64
#define REP  32
#define UNB  32    // nodes per (agg+update) block
#define SBLK 49    // ceil(NN/1024) scan blocks
#define NBN  1563  // ceil(NN/32) node blocks
#define NBC  1954  // ceil(2*NE/512) convert blocks
#define NBS  1954  // ceil(NE/256) scatter blocks

// ---------------- device scratch (no allocations allowed) ----------------
// g_deg, g_sflag, g_gsum, g_gcnt start zero (static init) and are re-zeroed
// by their consumers each call, so every kernel_launch sees identical state.
__device__ __align__(16) float g_pa[NN*HID];        // x @ (Wn Wm_a)
__device__ __align__(16) float g_pb[NN*HID];        // x @ (Wn Wm_b)
__device__ __align__(16) float g_agg[NN*HID];       // normalized message means
__device__ __align__(16) float g_gsum[REP*NGR*HID]; // replicated graph sums
__device__ __align__(16) float g_gcnt[REP*NGR];
__device__ __align__(16) float g_WA[16*HID];        // Wn @ Wm_a
__device__ __align__(16) float g_WB[16*HID];        // Wn @ Wm_b
__device__ __align__(16) float g_WE2[8*HID];        // We @ Wm_c
__device__ __align__(16) float g_WU1[16*HID];       // Wn @ Wu_top
__device__ __align__(16) float g_bconst[HID];       // bn@Wm_a + bn@Wm_b + be@Wm_c + bm
__device__ __align__(16) float g_bup[HID];          // bn@Wu_top + bu
__device__ int  g_row[NE];
__device__ int  g_col[NE];
__device__ int  g_rank[NE];                         // within-destination rank
__device__ int2 g_epack[NE];                        // CSR payload: (src_row, edge_id)
__device__ int  g_deg[NN];
__device__ int  g_ptr[NN+1];
__device__ int  g_bsum[SBLK];
__device__ int  g_sflag[SBLK];
__device__ int  g_batchi[NN];

// ---------------- helpers ----------------
__device__ __forceinline__ void red_f32(float* p, float v) {
    asm volatile("red.global.add.f32 [%0], %1;" :: "l"(p), "f"(v) : "memory");
}
__device__ __forceinline__ unsigned long long splat2(float w) {
    unsigned long long r;
    asm("mov.b64 %0, {%1, %1};" : "=l"(r) : "r"(__float_as_uint(w)));
    return r;
}
__device__ __forceinline__ unsigned long long pack2(float a, float b) {
    unsigned long long r;
    asm("mov.b64 %0, {%1, %2};" : "=l"(r) : "r"(__float_as_uint(a)), "r"(__float_as_uint(b)));
    return r;
}
__device__ __forceinline__ void unpack2(unsigned long long v, float& a, float& b) {
    unsigned lo, hi;
    asm("mov.b64 {%0, %1}, %2;" : "=r"(lo), "=r"(hi) : "l"(v));
    a = __uint_as_float(lo); b = __uint_as_float(hi);
}
__device__ __forceinline__ void fma_f32x2(unsigned long long& d,
                                          unsigned long long a,
                                          unsigned long long b) {
    asm("fma.rn.f32x2 %0, %1, %2, %0;" : "+l"(d) : "l"(a), "l"(b));
}
__device__ __forceinline__ unsigned long long add_f32x2(unsigned long long a,
                                                        unsigned long long b) {
    unsigned long long r;
    asm("add.rn.f32x2 %0, %1, %2;" : "=l"(r) : "l"(a), "l"(b));
    return r;
}

// ---------------- 1: fused weight-fold (blocks 0..56) + convert (rest) ----------------
__global__ __launch_bounds__(512) void k_prepconvert(
        const void* __restrict__ ei, const void* __restrict__ batch,
        const float* __restrict__ Wn, const float* __restrict__ bn,
        const float* __restrict__ We, const float* __restrict__ be,
        const float* __restrict__ Wm, const float* __restrict__ bm,
        const float* __restrict__ Wu, const float* __restrict__ bu) {
    const int t = threadIdx.x;
    const int b = blockIdx.x;

    if (b >= 57) {                     // ---- convert: indices + histogram + rank ----
        int i = (b - 57) * 512 + t;
        const int* ei32 = (const int*)ei;
        bool active = (i < 2*NE);
        int j = (i < NE) ? i : i - NE;
        int hw = active ? ei32[2*j + 1] : 0;
        unsigned m = __ballot_sync(0xffffffffu, active && (hw != 0));
        const bool f64 = (m == 0u);    // int64: all odd words zero
        if (active) {
            int v = f64 ? (int)((const long long*)ei)[i] : ei32[i];
            if (i < NE) {
                g_row[i] = v;
            } else {
                int r = atomicAdd(&g_deg[v], 1);
                g_col[i - NE]  = v;
                g_rank[i - NE] = r;
            }
        }
        if (i < NN) {
            g_batchi[i] = f64 ? (int)((const long long*)batch)[i] : ((const int*)batch)[i];
        }
        return;
    }

    // ---- prep: split-K weight folds ----
    __shared__ float swl[HID];
    __shared__ float sred[4][HID];
    __shared__ float sred4[4][4][HID];
    __shared__ float sbn[HID], sbe[HID];
    const int c = t & 127;
    const int q = t >> 7;

    if (b < 56) {
        const float* Wl;
        const float* Wr;
        float* out;
        int orow;
        if (b < 48) {
            int grp = b >> 4;
            orow = b & 15;
            Wl = Wn + orow*HID;
            if      (grp == 0) { Wr = Wm;           out = g_WA;  }
            else if (grp == 1) { Wr = Wm + HID*HID; out = g_WB;  }
            else               { Wr = Wu;           out = g_WU1; }
        } else {
            orow = b - 48;
            Wl = We + orow*HID;
            Wr = Wm + 2*HID*HID;
            out = g_WE2;
        }
        if (t < HID) swl[t] = Wl[t];
        __syncthreads();
        float a0 = 0.f, a1 = 0.f;
        const int k0 = 32*q;
        #pragma unroll
        for (int kk = 0; kk < 32; kk += 2) {
            a0 += swl[k0+kk]   * Wr[(k0+kk)*HID + c];
            a1 += swl[k0+kk+1] * Wr[(k0+kk+1)*HID + c];
        }
        sred[q][c] = a0 + a1;
        __syncthreads();
        if (q == 0)
            out[orow*HID + c] = (sred[0][c] + sred[1][c]) + (sred[2][c] + sred[3][c]);
    } else {
        if (t < HID) { sbn[t] = bn[t]; sbe[t] = be[t]; }
        __syncthreads();
        float p0 = 0.f, p1 = 0.f, p2 = 0.f, p3 = 0.f;
        const int k0 = 32*q;
        #pragma unroll
        for (int kk = 0; kk < 32; kk++) {
            int k = k0 + kk;
            float bnk = sbn[k];
            p0 += bnk    * Wm[k*HID + c];
            p1 += bnk    * Wm[(HID + k)*HID + c];
            p2 += sbe[k] * Wm[(2*HID + k)*HID + c];
            p3 += bnk    * Wu[k*HID + c];
        }
        sred4[q][0][c] = p0; sred4[q][1][c] = p1;
        sred4[q][2][c] = p2; sred4[q][3][c] = p3;
        __syncthreads();
        if (q == 0) {
            float b0 = sred4[0][0][c]+sred4[1][0][c]+sred4[2][0][c]+sred4[3][0][c];
            float b1 = sred4[0][1][c]+sred4[1][1][c]+sred4[2][1][c]+sred4[3][1][c];
            float b2 = sred4[0][2][c]+sred4[1][2][c]+sred4[2][2][c]+sred4[3][2][c];
            float u0 = sred4[0][3][c]+sred4[1][3][c]+sred4[2][3][c]+sred4[3][3][c];
            g_bconst[c] = bm[c] + b0 + b1 + b2;
            g_bup[c]    = bu[c] + u0;
        }
    }
}

// ---------------- 2: fused exclusive scan (decoupled lookback), clears g_deg ----------------
__global__ __launch_bounds__(1024) void k_scan() {
    __shared__ int swsum[32];
    __shared__ int soff;
    int t = threadIdx.x, b = blockIdx.x;
    int idx = b * 1024 + t;
    int lane = t & 31, warp = t >> 5;
    int d = (idx < NN) ? g_deg[idx] : 0;
    if (idx < NN) g_deg[idx] = 0;            // consume-and-clear for next call

    int v = d;
    #pragma unroll
    for (int o = 1; o < 32; o <<= 1) {
        int u = __shfl_up_sync(0xffffffffu, v, o);
        if (lane >= o) v += u;
    }
    if (lane == 31) swsum[warp] = v;
    __syncthreads();
    if (warp == 0) {
        int s = swsum[lane];
        #pragma unroll
        for (int o = 1; o < 32; o <<= 1) {
            int u = __shfl_up_sync(0xffffffffu, s, o);
            if (lane >= o) s += u;
        }
        swsum[lane] = s;
    }
    __syncthreads();
    int incl = v + ((warp > 0) ? swsum[warp - 1] : 0);

    if (t == 1023) {                          // publish block total
        g_bsum[b] = incl;
        __threadfence();
        atomicExch(&g_sflag[b], 1);
    }
    if (t < 32) {                             // lookback over predecessors
        int acc = 0;
        for (int j = t; j < b; j += 32) {
            while (atomicAdd(&g_sflag[j], 0) == 0) {}
            acc += atomicAdd(&g_bsum[j], 0);
        }
        #pragma unroll
        for (int o = 16; o > 0; o >>= 1) acc += __shfl_down_sync(0xffffffffu, acc, o);
        if (t == 0) soff = acc;
    }
    __syncthreads();
    if (idx < NN) g_ptr[idx] = (incl - d) + soff;
    if (b == 0 && t == 0) g_ptr[NN] = NE;     // degree sum is NE by construction
}

// ---------------- 3: fused node projections (blocks 0..NBN-1) + scatter (rest) ----------------
__global__ __launch_bounds__(256) void k_scatternode(const float* __restrict__ x) {
    const int t = threadIdx.x;
    const int b = blockIdx.x;

    if (b >= NBN) {                    // ---- scatter (pure stores) + clear sflag ----
        int i = (b - NBN) * 256 + t;
        if (i < NE) {
            int c = g_col[i];
            g_epack[g_ptr[c] + g_rank[i]] = make_int2(g_row[i], i);
        }
        if (i < SBLK) g_sflag[i] = 0;  // consume-and-clear for next call
        return;
    }

    // ---- node: pa/pb via channel-per-thread, broadcast LDS, f32x2 ----
    __shared__ __align__(16) float sxT[16][36];   // [i][n], 144B rows
    const int n0 = b * 32;
    #pragma unroll
    for (int r = 0; r < 2; r++) {
        int f = t + 256*r;             // 512 elements = 32 nodes x 16 feats
        int n = f >> 4, i = f & 15;
        int node = n0 + n;
        sxT[i][n] = (node < NN) ? x[(long long)node*16 + i] : 0.f;
    }
    __syncthreads();

    const int ch  = t & 127;
    const float* W   = (t >= 128) ? g_WB : g_WA;
    float*       OUT = (t >= 128) ? g_pb : g_pa;

    unsigned long long acc2[16];
    #pragma unroll
    for (int p = 0; p < 16; p++) acc2[p] = 0ULL;

    #pragma unroll
    for (int i = 0; i < 16; i++) {
        unsigned long long w2 = splat2(W[i*HID + ch]);
        const ulonglong2* srow = (const ulonglong2*)&sxT[i][0];
        #pragma unroll
        for (int qq = 0; qq < 8; qq++) {
            ulonglong2 a = srow[qq];   // broadcast (all lanes same addr)
            fma_f32x2(acc2[2*qq],   a.x, w2);
            fma_f32x2(acc2[2*qq+1], a.y, w2);
        }
    }
    #pragma unroll
    for (int p = 0; p < 16; p++) {
        float v0, v1;
        unpack2(acc2[p], v0, v1);
        int na = n0 + 2*p, nb2 = n0 + 2*p + 1;
        if (na  < NN) OUT[(long long)na *HID + ch] = v0;   // coalesced across ch
        if (nb2 < NN) OUT[(long long)nb2*HID + ch] = v1;
    }
}

// ---------------- 4: FUSED agg + update — block owns 32 nodes end-to-end ----------------
// Phase A: 4 warps x 8 nodes run CSR aggregation, write g_agg for OWN nodes.
// __syncthreads() orders those global writes block-locally.
// Phase B: node update + graph pooling reading back the same 32 nodes (L2-hot).
__global__ __launch_bounds__(128) void k_aggupdate(const float* __restrict__ ea,
                                                   const float* __restrict__ x,
                                                   const float* __restrict__ Wu) {
    __shared__ float4 sbc[32];
    __shared__ __align__(16) float saggT[HID][UNB + 4];
    __shared__ __align__(16) float sxT[16][UNB + 4];
    __shared__ int sbatch[UNB];

    const int t = threadIdx.x;
    const int warp = t >> 5, lane = t & 31;
    const int n0 = blockIdx.x * UNB;

    // ---- phase A: aggregation ----
    unsigned long long wx[8], wy[8];   // WE2[j][4*lane..4*lane+3] per lane
    #pragma unroll
    for (int j = 0; j < 8; j++) {
        ulonglong2 w = ((const ulonglong2*)g_WE2)[j*32 + lane];
        wx[j] = w.x; wy[j] = w.y;
    }
    if (t < 32) sbc[t] = ((const float4*)g_bconst)[t];
    __syncthreads();

    for (int s = 0; s < 8; s++) {
        int node = n0 + s*4 + warp;     // round-robin nodes over warps
        if (node >= NN) continue;
        int beg = g_ptr[node];
        int end = g_ptr[node + 1];

        float4 pbv = ((const float4*)g_pb)[node*32 + lane];
        float4 bc  = sbc[lane];
        unsigned long long bx0 = pack2(pbv.x + bc.x, pbv.y + bc.y);
        unsigned long long bx1 = pack2(pbv.z + bc.z, pbv.w + bc.w);

        float4 acc = {0.f, 0.f, 0.f, 0.f};
        int2 e1 = {0,0}, e2 = {0,0};
        ulonglong2 pav = {0ULL, 0ULL};
        float4 A = {0,0,0,0}, B = {0,0,0,0};
        if (beg < end)     e1 = g_epack[beg];
        if (beg + 1 < end) e2 = g_epack[beg + 1];
        if (beg < end) {
            pav = ((const ulonglong2*)g_pa)[e1.x*32 + lane];
            const float4* eap = (const float4*)(ea + (long long)e1.y*8);
            A = eap[0]; B = eap[1];
        }
        for (int p = beg; p < end; p++) {
            ulonglong2 pc = pav;
            float4 Ac = A, Bc = B;
            e1 = e2;
            if (p + 2 < end) e2 = g_epack[p + 2];
            if (p + 1 < end) {
                pav = ((const ulonglong2*)g_pa)[e1.x*32 + lane];
                const float4* eap = (const float4*)(ea + (long long)e1.y*8);
                A = eap[0]; B = eap[1];
            }
            unsigned long long m0 = add_f32x2(pc.x, bx0);
            unsigned long long m1 = add_f32x2(pc.y, bx1);
            float ej[8] = {Ac.x, Ac.y, Ac.z, Ac.w, Bc.x, Bc.y, Bc.z, Bc.w};
            #pragma unroll
            for (int j = 0; j < 8; j++) {
                unsigned long long ej2 = splat2(ej[j]);
                fma_f32x2(m0, ej2, wx[j]);
                fma_f32x2(m1, ej2, wy[j]);
            }
            float f0, f1, f2, f3;
            unpack2(m0, f0, f1);
            unpack2(m1, f2, f3);
            acc.x += fmaxf(f0, 0.f);
            acc.y += fmaxf(f1, 0.f);
            acc.z += fmaxf(f2, 0.f);
            acc.w += fmaxf(f3, 0.f);
        }
        float inv = 1.f / fmaxf((float)(end - beg), 1.f);
        acc.x *= inv; acc.y *= inv; acc.z *= inv; acc.w *= inv;
        ((float4*)g_agg)[node*32 + lane] = acc;
    }
    __syncthreads();   // orders our g_agg writes for the whole block

    // ---- phase B: update + pooling (reads back OWN nodes only) ----
    if (t < UNB) {
        int node = n0 + t;
        sbatch[t] = (node < NN) ? g_batchi[node] : 0;
    }
    for (int n = 0; n < UNB; n++) {
        int node = n0 + n;
        saggT[t][n] = (node < NN) ? g_agg[node*HID + t] : 0.f;
    }
    for (int idx = t; idx < 16*UNB; idx += 128) {
        int n = idx & 31, i = idx >> 5;
        int node = n0 + n;
        sxT[i][n] = (node < NN) ? x[node*16 + i] : 0.f;
    }
    __syncthreads();

    const int c = t;
    unsigned long long acc2[UNB/2];
    #pragma unroll
    for (int p = 0; p < UNB/2; p++) acc2[p] = 0ULL;

    #pragma unroll
    for (int i = 0; i < 16; i++) {
        unsigned long long w2 = splat2(g_WU1[i*HID + c]);
        const ulonglong2* srow = (const ulonglong2*)&sxT[i][0];
        #pragma unroll
        for (int q = 0; q < UNB/4; q++) {
            ulonglong2 a = srow[q];
            fma_f32x2(acc2[2*q],   a.x, w2);
            fma_f32x2(acc2[2*q+1], a.y, w2);
        }
    }
    for (int k = 0; k < HID; k++) {
        unsigned long long w2 = splat2(Wu[(HID + k)*HID + c]);   // Wu_bot
        const ulonglong2* srow = (const ulonglong2*)&saggT[k][0];
        #pragma unroll
        for (int q = 0; q < UNB/4; q++) {
            ulonglong2 a = srow[q];
            fma_f32x2(acc2[2*q],   a.x, w2);
            fma_f32x2(acc2[2*q+1], a.y, w2);
        }
    }

    float bupv = g_bup[c];
    int   rep  = blockIdx.x & (REP - 1);
    float* gsbase = &g_gsum[rep*NGR*HID];
    int   cur = sbatch[0];
    float sum = 0.f;
    #pragma unroll
    for (int p = 0; p < UNB/2; p++) {
        float hv[2];
        unpack2(acc2[p], hv[0], hv[1]);
        #pragma unroll
        for (int q = 0; q < 2; q++) {
            int n = 2*p + q;
            int node = n0 + n;
            if (node < NN) {
                float h = fmaxf(hv[q] + bupv, 0.f);
                int b = sbatch[n];
                if (b != cur) {
                    red_f32(gsbase + cur*HID + c, sum);
                    cur = b; sum = 0.f;
                }
                sum += h;
            }
        }
    }
    red_f32(gsbase + cur*HID + c, sum);

    if (t < UNB) {
        int node = n0 + t;
        if (node < NN) red_f32(&g_gcnt[rep*NGR + sbatch[t]], 1.0f);
    }
}

// ---------------- 5: readout MLP, clears g_gsum/g_gcnt ----------------
__global__ __launch_bounds__(128) void k_final(const float* __restrict__ Wr1,
                                               const float* __restrict__ br1,
                                               const float* __restrict__ Wr2,
                                               const float* __restrict__ br2,
                                               float* __restrict__ out) {
    __shared__ float sg[HID];
    __shared__ float sred[4];
    int g = blockIdx.x, t = threadIdx.x;
    float s = 0.f;
    for (int r = 0; r < REP; r++) s += g_gsum[r*NGR*HID + g*HID + t];
    float gc = 0.f;
    for (int r = 0; r < REP; r++) gc += g_gcnt[r*NGR + g];
    sg[t] = s / fmaxf(gc, 1.f);
    __syncthreads();
    // consume-and-clear (this block owns graph g's slots)
    for (int r = 0; r < REP; r++) g_gsum[r*NGR*HID + g*HID + t] = 0.f;
    if (t == 0) for (int r = 0; r < REP; r++) g_gcnt[r*NGR + g] = 0.f;

    float acc = br1[t];
    for (int k = 0; k < HID; k++) acc += sg[k] * Wr1[k*HID + t];
    acc = fmaxf(acc, 0.f);
    float v = acc * Wr2[t];
    #pragma unroll
    for (int o = 16; o > 0; o >>= 1) v += __shfl_down_sync(0xffffffffu, v, o);
    if ((t & 31) == 0) sred[t >> 5] = v;
    __syncthreads();
    if (t == 0) out[g] = sred[0] + sred[1] + sred[2] + sred[3] + br2[0];
}

// ---------------- launch ----------------
extern "C" void kernel_launch(void* const* d_in, const int* in_sizes, int n_in,
                              void* d_out, int out_size) {
    const float* x     = (const float*)d_in[0];
    const float* ea    = (const float*)d_in[1];
    const void*  ei    = d_in[2];
    const void*  batch = d_in[3];
    const float* Wn  = (const float*)d_in[4];
    const float* bn  = (const float*)d_in[5];
    const float* We  = (const float*)d_in[6];
    const float* be  = (const float*)d_in[7];
    const float* Wm  = (const float*)d_in[8];
    const float* bm  = (const float*)d_in[9];
    const float* Wu  = (const float*)d_in[10];
    const float* bu  = (const float*)d_in[11];
    const float* Wr1 = (const float*)d_in[12];
    const float* br1 = (const float*)d_in[13];
    const float* Wr2 = (const float*)d_in[14];
    const float* br2 = (const float*)d_in[15];
    float* out = (float*)d_out;

    k_prepconvert <<<57 + NBC, 512>>>(ei, batch, Wn, bn, We, be, Wm, bm, Wu, bu);
    k_scan        <<<SBLK, 1024>>>();
    k_scatternode <<<NBN + NBS, 256>>>(x);
    k_aggupdate   <<<NBN, 128>>>(ea, x, Wu);     // launch #4 -> profiled
    k_final       <<<NGR, 128>>>(Wr1, br1, Wr2, br2, out);
}

// round 14
// speedup vs baseline: 1.3614x; 1.0308x over previous
#include <cuda_runtime.h>

#define NN   50000
#define NE   500000
#define HID  128
#define NGR  64
#define REP  32
#define UNB  32    // nodes per (agg+update) block
#define SBLK 49    // ceil(NN/1024) scan blocks
#define NBN  1563  // ceil(NN/32) node blocks
#define NBC  1954  // ceil(2*NE/512) convert blocks
#define NBS  1954  // ceil(NE/256) scatter blocks

// ---------------- device scratch (no allocations allowed) ----------------
// g_deg, g_sflag, g_gsum, g_gcnt start zero (static init) and are re-zeroed
// by their consumers each call, so every kernel_launch sees identical state.
__device__ __align__(16) float g_pa[NN*HID];        // x @ (Wn Wm_a)
__device__ __align__(16) float g_pb[NN*HID];        // x @ (Wn Wm_b)
__device__ __align__(16) float g_agg[NN*HID];       // normalized message means
__device__ __align__(16) float g_gsum[REP*NGR*HID]; // replicated graph sums
__device__ __align__(16) float g_gcnt[REP*NGR];
__device__ __align__(16) float g_WA[16*HID];        // Wn @ Wm_a
__device__ __align__(16) float g_WB[16*HID];        // Wn @ Wm_b
__device__ __align__(16) float g_WE2[8*HID];        // We @ Wm_c
__device__ __align__(16) float g_WU1[16*HID];       // Wn @ Wu_top
__device__ __align__(16) float g_bconst[HID];       // bn@Wm_a + bn@Wm_b + be@Wm_c + bm
__device__ __align__(16) float g_bup[HID];          // bn@Wu_top + bu
__device__ int  g_row[NE];
__device__ int  g_col[NE];
__device__ int  g_rank[NE];                         // within-destination rank
__device__ int2 g_epack[NE];                        // CSR payload: (src_row, edge_id)
__device__ int  g_deg[NN];
__device__ int  g_ptr[NN+1];
__device__ int  g_bsum[SBLK];
__device__ int  g_sflag[SBLK];
__device__ int  g_batchi[NN];

// ---------------- helpers ----------------
__device__ __forceinline__ void red_f32(float* p, float v) {
    asm volatile("red.global.add.f32 [%0], %1;" :: "l"(p), "f"(v) : "memory");
}
__device__ __forceinline__ unsigned long long splat2(float w) {
    unsigned long long r;
    asm("mov.b64 %0, {%1, %1};" : "=l"(r) : "r"(__float_as_uint(w)));
    return r;
}
__device__ __forceinline__ unsigned long long pack2(float a, float b) {
    unsigned long long r;
    asm("mov.b64 %0, {%1, %2};" : "=l"(r) : "r"(__float_as_uint(a)), "r"(__float_as_uint(b)));
    return r;
}
__device__ __forceinline__ void unpack2(unsigned long long v, float& a, float& b) {
    unsigned lo, hi;
    asm("mov.b64 {%0, %1}, %2;" : "=r"(lo), "=r"(hi) : "l"(v));
    a = __uint_as_float(lo); b = __uint_as_float(hi);
}
__device__ __forceinline__ void fma_f32x2(unsigned long long& d,
                                          unsigned long long a,
                                          unsigned long long b) {
    asm("fma.rn.f32x2 %0, %1, %2, %0;" : "+l"(d) : "l"(a), "l"(b));
}
__device__ __forceinline__ unsigned long long add_f32x2(unsigned long long a,
                                                        unsigned long long b) {
    unsigned long long r;
    asm("add.rn.f32x2 %0, %1, %2;" : "=l"(r) : "l"(a), "l"(b));
    return r;
}

// ---------------- 1: fused weight-fold (blocks 0..56) + convert (rest) ----------------
__global__ __launch_bounds__(512) void k_prepconvert(
        const void* __restrict__ ei, const void* __restrict__ batch,
        const float* __restrict__ Wn, const float* __restrict__ bn,
        const float* __restrict__ We, const float* __restrict__ be,
        const float* __restrict__ Wm, const float* __restrict__ bm,
        const float* __restrict__ Wu, const float* __restrict__ bu) {
    const int t = threadIdx.x;
    const int b = blockIdx.x;

    if (b >= 57) {                     // ---- convert: indices + histogram + rank ----
        int i = (b - 57) * 512 + t;
        const int* ei32 = (const int*)ei;
        bool active = (i < 2*NE);
        int j = (i < NE) ? i : i - NE;
        int hw = active ? ei32[2*j + 1] : 0;
        unsigned m = __ballot_sync(0xffffffffu, active && (hw != 0));
        const bool f64 = (m == 0u);    // int64: all odd words zero
        if (active) {
            int v = f64 ? (int)((const long long*)ei)[i] : ei32[i];
            if (i < NE) {
                g_row[i] = v;
            } else {
                int r = atomicAdd(&g_deg[v], 1);
                g_col[i - NE]  = v;
                g_rank[i - NE] = r;
            }
        }
        if (i < NN) {
            g_batchi[i] = f64 ? (int)((const long long*)batch)[i] : ((const int*)batch)[i];
        }
        return;
    }

    // ---- prep: split-K weight folds ----
    __shared__ float swl[HID];
    __shared__ float sred[4][HID];
    __shared__ float sred4[4][4][HID];
    __shared__ float sbn[HID], sbe[HID];
    const int c = t & 127;
    const int q = t >> 7;

    if (b < 56) {
        const float* Wl;
        const float* Wr;
        float* out;
        int orow;
        if (b < 48) {
            int grp = b >> 4;
            orow = b & 15;
            Wl = Wn + orow*HID;
            if      (grp == 0) { Wr = Wm;           out = g_WA;  }
            else if (grp == 1) { Wr = Wm + HID*HID; out = g_WB;  }
            else               { Wr = Wu;           out = g_WU1; }
        } else {
            orow = b - 48;
            Wl = We + orow*HID;
            Wr = Wm + 2*HID*HID;
            out = g_WE2;
        }
        if (t < HID) swl[t] = Wl[t];
        __syncthreads();
        float a0 = 0.f, a1 = 0.f;
        const int k0 = 32*q;
        #pragma unroll
        for (int kk = 0; kk < 32; kk += 2) {
            a0 += swl[k0+kk]   * Wr[(k0+kk)*HID + c];
            a1 += swl[k0+kk+1] * Wr[(k0+kk+1)*HID + c];
        }
        sred[q][c] = a0 + a1;
        __syncthreads();
        if (q == 0)
            out[orow*HID + c] = (sred[0][c] + sred[1][c]) + (sred[2][c] + sred[3][c]);
    } else {
        if (t < HID) { sbn[t] = bn[t]; sbe[t] = be[t]; }
        __syncthreads();
        float p0 = 0.f, p1 = 0.f, p2 = 0.f, p3 = 0.f;
        const int k0 = 32*q;
        #pragma unroll
        for (int kk = 0; kk < 32; kk++) {
            int k = k0 + kk;
            float bnk = sbn[k];
            p0 += bnk    * Wm[k*HID + c];
            p1 += bnk    * Wm[(HID + k)*HID + c];
            p2 += sbe[k] * Wm[(2*HID + k)*HID + c];
            p3 += bnk    * Wu[k*HID + c];
        }
        sred4[q][0][c] = p0; sred4[q][1][c] = p1;
        sred4[q][2][c] = p2; sred4[q][3][c] = p3;
        __syncthreads();
        if (q == 0) {
            float b0 = sred4[0][0][c]+sred4[1][0][c]+sred4[2][0][c]+sred4[3][0][c];
            float b1 = sred4[0][1][c]+sred4[1][1][c]+sred4[2][1][c]+sred4[3][1][c];
            float b2 = sred4[0][2][c]+sred4[1][2][c]+sred4[2][2][c]+sred4[3][2][c];
            float u0 = sred4[0][3][c]+sred4[1][3][c]+sred4[2][3][c]+sred4[3][3][c];
            g_bconst[c] = bm[c] + b0 + b1 + b2;
            g_bup[c]    = bu[c] + u0;
        }
    }
}

// ---------------- 2: fused exclusive scan (decoupled lookback), clears g_deg ----------------
__global__ __launch_bounds__(1024) void k_scan() {
    __shared__ int swsum[32];
    __shared__ int soff;
    int t = threadIdx.x, b = blockIdx.x;
    int idx = b * 1024 + t;
    int lane = t & 31, warp = t >> 5;
    int d = (idx < NN) ? g_deg[idx] : 0;
    if (idx < NN) g_deg[idx] = 0;            // consume-and-clear for next call

    int v = d;
    #pragma unroll
    for (int o = 1; o < 32; o <<= 1) {
        int u = __shfl_up_sync(0xffffffffu, v, o);
        if (lane >= o) v += u;
    }
    if (lane == 31) swsum[warp] = v;
    __syncthreads();
    if (warp == 0) {
        int s = swsum[lane];
        #pragma unroll
        for (int o = 1; o < 32; o <<= 1) {
            int u = __shfl_up_sync(0xffffffffu, s, o);
            if (lane >= o) s += u;
        }
        swsum[lane] = s;
    }
    __syncthreads();
    int incl = v + ((warp > 0) ? swsum[warp - 1] : 0);

    if (t == 1023) {                          // publish block total
        g_bsum[b] = incl;
        __threadfence();
        atomicExch(&g_sflag[b], 1);
    }
    if (t < 32) {                             // lookback over predecessors
        int acc = 0;
        for (int j = t; j < b; j += 32) {
            while (atomicAdd(&g_sflag[j], 0) == 0) {}
            acc += atomicAdd(&g_bsum[j], 0);
        }
        #pragma unroll
        for (int o = 16; o > 0; o >>= 1) acc += __shfl_down_sync(0xffffffffu, acc, o);
        if (t == 0) soff = acc;
    }
    __syncthreads();
    if (idx < NN) g_ptr[idx] = (incl - d) + soff;
    if (b == 0 && t == 0) g_ptr[NN] = NE;     // degree sum is NE by construction
}

// ---------------- 3: fused node projections (blocks 0..NBN-1) + scatter (rest) ----------------
__global__ __launch_bounds__(256) void k_scatternode(const float* __restrict__ x) {
    const int t = threadIdx.x;
    const int b = blockIdx.x;

    if (b >= NBN) {                    // ---- scatter (pure stores) + clear sflag ----
        int i = (b - NBN) * 256 + t;
        if (i < NE) {
            int c = g_col[i];
            g_epack[g_ptr[c] + g_rank[i]] = make_int2(g_row[i], i);
        }
        if (i < SBLK) g_sflag[i] = 0;  // consume-and-clear for next call
        return;
    }

    // ---- node: pa/pb via channel-per-thread, broadcast LDS, f32x2 ----
    __shared__ __align__(16) float sxT[16][36];   // [i][n], 144B rows
    const int n0 = b * 32;
    #pragma unroll
    for (int r = 0; r < 2; r++) {
        int f = t + 256*r;             // 512 elements = 32 nodes x 16 feats
        int n = f >> 4, i = f & 15;
        int node = n0 + n;
        sxT[i][n] = (node < NN) ? x[(long long)node*16 + i] : 0.f;
    }
    __syncthreads();

    const int ch  = t & 127;
    const float* W   = (t >= 128) ? g_WB : g_WA;
    float*       OUT = (t >= 128) ? g_pb : g_pa;

    unsigned long long acc2[16];
    #pragma unroll
    for (int p = 0; p < 16; p++) acc2[p] = 0ULL;

    #pragma unroll
    for (int i = 0; i < 16; i++) {
        unsigned long long w2 = splat2(W[i*HID + ch]);
        const ulonglong2* srow = (const ulonglong2*)&sxT[i][0];
        #pragma unroll
        for (int qq = 0; qq < 8; qq++) {
            ulonglong2 a = srow[qq];   // broadcast (all lanes same addr)
            fma_f32x2(acc2[2*qq],   a.x, w2);
            fma_f32x2(acc2[2*qq+1], a.y, w2);
        }
    }
    #pragma unroll
    for (int p = 0; p < 16; p++) {
        float v0, v1;
        unpack2(acc2[p], v0, v1);
        int na = n0 + 2*p, nb2 = n0 + 2*p + 1;
        if (na  < NN) OUT[(long long)na *HID + ch] = v0;   // coalesced across ch
        if (nb2 < NN) OUT[(long long)nb2*HID + ch] = v1;
    }
}

// ---------------- 4: FUSED agg + update — 6 blocks/SM, Wu prefetch ----------------
__global__ __launch_bounds__(128, 6) void k_aggupdate(const float* __restrict__ ea,
                                                      const float* __restrict__ x,
                                                      const float* __restrict__ Wu) {
    __shared__ float4 sbc[32];
    __shared__ __align__(16) float saggT[HID][UNB + 4];
    __shared__ __align__(16) float sxT[16][UNB + 4];
    __shared__ int sbatch[UNB];

    const int t = threadIdx.x;
    const int warp = t >> 5, lane = t & 31;
    const int n0 = blockIdx.x * UNB;

    // ---- phase A: aggregation ----
    unsigned long long wx[8], wy[8];   // WE2[j][4*lane..4*lane+3] per lane
    #pragma unroll
    for (int j = 0; j < 8; j++) {
        ulonglong2 w = ((const ulonglong2*)g_WE2)[j*32 + lane];
        wx[j] = w.x; wy[j] = w.y;
    }
    if (t < 32) sbc[t] = ((const float4*)g_bconst)[t];
    __syncthreads();

    for (int s = 0; s < 8; s++) {
        int node = n0 + s*4 + warp;     // round-robin nodes over warps
        if (node >= NN) continue;
        int beg = g_ptr[node];
        int end = g_ptr[node + 1];

        float4 pbv = ((const float4*)g_pb)[node*32 + lane];
        float4 bc  = sbc[lane];
        unsigned long long bx0 = pack2(pbv.x + bc.x, pbv.y + bc.y);
        unsigned long long bx1 = pack2(pbv.z + bc.z, pbv.w + bc.w);

        float4 acc = {0.f, 0.f, 0.f, 0.f};
        int2 e1 = {0,0}, e2 = {0,0};
        ulonglong2 pav = {0ULL, 0ULL};
        float4 A = {0,0,0,0}, B = {0,0,0,0};
        if (beg < end)     e1 = g_epack[beg];
        if (beg + 1 < end) e2 = g_epack[beg + 1];
        if (beg < end) {
            pav = ((const ulonglong2*)g_pa)[e1.x*32 + lane];
            const float4* eap = (const float4*)(ea + (long long)e1.y*8);
            A = eap[0]; B = eap[1];
        }
        for (int p = beg; p < end; p++) {
            ulonglong2 pc = pav;
            float4 Ac = A, Bc = B;
            e1 = e2;
            if (p + 2 < end) e2 = g_epack[p + 2];
            if (p + 1 < end) {
                pav = ((const ulonglong2*)g_pa)[e1.x*32 + lane];
                const float4* eap = (const float4*)(ea + (long long)e1.y*8);
                A = eap[0]; B = eap[1];
            }
            unsigned long long m0 = add_f32x2(pc.x, bx0);
            unsigned long long m1 = add_f32x2(pc.y, bx1);
            float ej[8] = {Ac.x, Ac.y, Ac.z, Ac.w, Bc.x, Bc.y, Bc.z, Bc.w};
            #pragma unroll
            for (int j = 0; j < 8; j++) {
                unsigned long long ej2 = splat2(ej[j]);
                fma_f32x2(m0, ej2, wx[j]);
                fma_f32x2(m1, ej2, wy[j]);
            }
            float f0, f1, f2, f3;
            unpack2(m0, f0, f1);
            unpack2(m1, f2, f3);
            acc.x += fmaxf(f0, 0.f);
            acc.y += fmaxf(f1, 0.f);
            acc.z += fmaxf(f2, 0.f);
            acc.w += fmaxf(f3, 0.f);
        }
        float inv = 1.f / fmaxf((float)(end - beg), 1.f);
        acc.x *= inv; acc.y *= inv; acc.z *= inv; acc.w *= inv;
        ((float4*)g_agg)[node*32 + lane] = acc;
    }
    __syncthreads();   // orders our g_agg writes for the whole block

    // ---- phase B: update + pooling (reads back OWN nodes only) ----
    if (t < UNB) {
        int node = n0 + t;
        sbatch[t] = (node < NN) ? g_batchi[node] : 0;
    }
    for (int n = 0; n < UNB; n++) {
        int node = n0 + n;
        saggT[t][n] = (node < NN) ? g_agg[node*HID + t] : 0.f;
    }
    for (int idx = t; idx < 16*UNB; idx += 128) {
        int n = idx & 31, i = idx >> 5;
        int node = n0 + n;
        sxT[i][n] = (node < NN) ? x[node*16 + i] : 0.f;
    }
    __syncthreads();

    const int c = t;
    unsigned long long acc2[UNB/2];
    #pragma unroll
    for (int p = 0; p < UNB/2; p++) acc2[p] = 0ULL;

    #pragma unroll
    for (int i = 0; i < 16; i++) {
        unsigned long long w2 = splat2(g_WU1[i*HID + c]);
        const ulonglong2* srow = (const ulonglong2*)&sxT[i][0];
        #pragma unroll
        for (int q = 0; q < UNB/4; q++) {
            ulonglong2 a = srow[q];
            fma_f32x2(acc2[2*q],   a.x, w2);
            fma_f32x2(acc2[2*q+1], a.y, w2);
        }
    }
    // Wu_bot loop with explicit 1-ahead weight prefetch
    {
        const float* wub = Wu + HID*HID + c;
        float wnext = wub[0];
        #pragma unroll 4
        for (int k = 0; k < HID; k++) {
            float wcur = wnext;
            if (k + 1 < HID) wnext = wub[(k + 1) * HID];
            unsigned long long w2 = splat2(wcur);
            const ulonglong2* srow = (const ulonglong2*)&saggT[k][0];
            #pragma unroll
            for (int q = 0; q < UNB/4; q++) {
                ulonglong2 a = srow[q];
                fma_f32x2(acc2[2*q],   a.x, w2);
                fma_f32x2(acc2[2*q+1], a.y, w2);
            }
        }
    }

    float bupv = g_bup[c];
    int   rep  = blockIdx.x & (REP - 1);
    float* gsbase = &g_gsum[rep*NGR*HID];
    int   cur = sbatch[0];
    float sum = 0.f;
    #pragma unroll
    for (int p = 0; p < UNB/2; p++) {
        float hv[2];
        unpack2(acc2[p], hv[0], hv[1]);
        #pragma unroll
        for (int q = 0; q < 2; q++) {
            int n = 2*p + q;
            int node = n0 + n;
            if (node < NN) {
                float h = fmaxf(hv[q] + bupv, 0.f);
                int b = sbatch[n];
                if (b != cur) {
                    red_f32(gsbase + cur*HID + c, sum);
                    cur = b; sum = 0.f;
                }
                sum += h;
            }
        }
    }
    red_f32(gsbase + cur*HID + c, sum);

    if (t < UNB) {
        int node = n0 + t;
        if (node < NN) red_f32(&g_gcnt[rep*NGR + sbatch[t]], 1.0f);
    }
}

// ---------------- 5: readout MLP, clears g_gsum/g_gcnt ----------------
__global__ __launch_bounds__(128) void k_final(const float* __restrict__ Wr1,
                                               const float* __restrict__ br1,
                                               const float* __restrict__ Wr2,
                                               const float* __restrict__ br2,
                                               float* __restrict__ out) {
    __shared__ float sg[HID];
    __shared__ float sred[4];
    int g = blockIdx.x, t = threadIdx.x;
    float s = 0.f;
    for (int r = 0; r < REP; r++) s += g_gsum[r*NGR*HID + g*HID + t];
    float gc = 0.f;
    for (int r = 0; r < REP; r++) gc += g_gcnt[r*NGR + g];
    sg[t] = s / fmaxf(gc, 1.f);
    __syncthreads();
    // consume-and-clear (this block owns graph g's slots)
    for (int r = 0; r < REP; r++) g_gsum[r*NGR*HID + g*HID + t] = 0.f;
    if (t == 0) for (int r = 0; r < REP; r++) g_gcnt[r*NGR + g] = 0.f;

    float acc = br1[t];
    for (int k = 0; k < HID; k++) acc += sg[k] * Wr1[k*HID + t];
    acc = fmaxf(acc, 0.f);
    float v = acc * Wr2[t];
    #pragma unroll
    for (int o = 16; o > 0; o >>= 1) v += __shfl_down_sync(0xffffffffu, v, o);
    if ((t & 31) == 0) sred[t >> 5] = v;
    __syncthreads();
    if (t == 0) out[g] = sred[0] + sred[1] + sred[2] + sred[3] + br2[0];
}

// ---------------- launch ----------------
extern "C" void kernel_launch(void* const* d_in, const int* in_sizes, int n_in,
                              void* d_out, int out_size) {
    const float* x     = (const float*)d_in[0];
    const float* ea    = (const float*)d_in[1];
    const void*  ei    = d_in[2];
    const void*  batch = d_in[3];
    const float* Wn  = (const float*)d_in[4];
    const float* bn  = (const float*)d_in[5];
    const float* We  = (const float*)d_in[6];
    const float* be  = (const float*)d_in[7];
    const float* Wm  = (const float*)d_in[8];
    const float* bm  = (const float*)d_in[9];
    const float* Wu  = (const float*)d_in[10];
    const float* bu  = (const float*)d_in[11];
    const float* Wr1 = (const float*)d_in[12];
    const float* br1 = (const float*)d_in[13];
    const float* Wr2 = (const float*)d_in[14];
    const float* br2 = (const float*)d_in[15];
    float* out = (float*)d_out;

    k_prepconvert <<<57 + NBC, 512>>>(ei, batch, Wn, bn, We, be, Wm, bm, Wu, bu);
    k_scan        <<<SBLK, 1024>>>();
    k_scatternode <<<NBN + NBS, 256>>>(x);
    k_aggupdate   <<<NBN, 128>>>(ea, x, Wu);     // launch #4 -> profiled
    k_final       <<<NGR, 128>>>(Wr1, br1, Wr2, br2, out);
}

// round 16
// speedup vs baseline: 1.4534x; 1.0675x over previous
#include <cuda_runtime.h>

#define NN   50000
#define NE   500000
#define HID  128
#define NGR  64
#define REP  32
#define UNB  32    // nodes per (agg+update) block
#define SBLK 49    // ceil(NN/1024) scan blocks
#define NBN  1563  // ceil(NN/32) node blocks
#define NBC  1954  // ceil(2*NE/512) convert blocks
#define NBS  1954  // ceil(NE/256) scatter blocks

// ---------------- device scratch (no allocations allowed) ----------------
// g_deg, g_sflag, g_gsum, g_gcnt start zero (static init) and are re-zeroed
// by their consumers each call, so every kernel_launch sees identical state.
__device__ __align__(16) float g_pa[NN*HID];        // x @ (Wn Wm_a)
__device__ __align__(16) float g_pb[NN*HID];        // x @ (Wn Wm_b)
__device__ __align__(16) float g_gsum[REP*NGR*HID]; // replicated graph sums
__device__ __align__(16) float g_gcnt[REP*NGR];
__device__ __align__(16) float g_WA[16*HID];        // Wn @ Wm_a
__device__ __align__(16) float g_WB[16*HID];        // Wn @ Wm_b
__device__ __align__(16) float g_WE2[8*HID];        // We @ Wm_c
__device__ __align__(16) float g_WU1[16*HID];       // Wn @ Wu_top
__device__ __align__(16) float g_bconst[HID];       // bn@Wm_a + bn@Wm_b + be@Wm_c + bm
__device__ __align__(16) float g_bup[HID];          // bn@Wu_top + bu
__device__ int  g_row[NE];
__device__ int  g_col[NE];
__device__ int  g_rank[NE];                         // within-destination rank
__device__ int2 g_epack[NE];                        // CSR payload: (src_row, edge_id)
__device__ int  g_deg[NN];
__device__ int  g_ptr[NN+1];
__device__ int  g_bsum[SBLK];
__device__ int  g_sflag[SBLK];
__device__ int  g_batchi[NN];

// ---------------- helpers ----------------
__device__ __forceinline__ void red_f32(float* p, float v) {
    asm volatile("red.global.add.f32 [%0], %1;" :: "l"(p), "f"(v) : "memory");
}
__device__ __forceinline__ unsigned long long splat2(float w) {
    unsigned long long r;
    asm("mov.b64 %0, {%1, %1};" : "=l"(r) : "r"(__float_as_uint(w)));
    return r;
}
__device__ __forceinline__ unsigned long long pack2(float a, float b) {
    unsigned long long r;
    asm("mov.b64 %0, {%1, %2};" : "=l"(r) : "r"(__float_as_uint(a)), "r"(__float_as_uint(b)));
    return r;
}
__device__ __forceinline__ void unpack2(unsigned long long v, float& a, float& b) {
    unsigned lo, hi;
    asm("mov.b64 {%0, %1}, %2;" : "=r"(lo), "=r"(hi) : "l"(v));
    a = __uint_as_float(lo); b = __uint_as_float(hi);
}
__device__ __forceinline__ void fma_f32x2(unsigned long long& d,
                                          unsigned long long a,
                                          unsigned long long b) {
    asm("fma.rn.f32x2 %0, %1, %2, %0;" : "+l"(d) : "l"(a), "l"(b));
}
__device__ __forceinline__ unsigned long long add_f32x2(unsigned long long a,
                                                        unsigned long long b) {
    unsigned long long r;
    asm("add.rn.f32x2 %0, %1, %2;" : "=l"(r) : "l"(a), "l"(b));
    return r;
}

// ---------------- 1: fused weight-fold (blocks 0..56) + convert (rest) ----------------
__global__ __launch_bounds__(512) void k_prepconvert(
        const void* __restrict__ ei, const void* __restrict__ batch,
        const float* __restrict__ Wn, const float* __restrict__ bn,
        const float* __restrict__ We, const float* __restrict__ be,
        const float* __restrict__ Wm, const float* __restrict__ bm,
        const float* __restrict__ Wu, const float* __restrict__ bu) {
    const int t = threadIdx.x;
    const int b = blockIdx.x;

    if (b >= 57) {                     // ---- convert: indices + histogram + rank ----
        int i = (b - 57) * 512 + t;
        const int* ei32 = (const int*)ei;
        bool active = (i < 2*NE);
        int j = (i < NE) ? i : i - NE;
        int hw = active ? ei32[2*j + 1] : 0;
        unsigned m = __ballot_sync(0xffffffffu, active && (hw != 0));
        const bool f64 = (m == 0u);    // int64: all odd words zero
        if (active) {
            int v = f64 ? (int)((const long long*)ei)[i] : ei32[i];
            if (i < NE) {
                g_row[i] = v;
            } else {
                int r = atomicAdd(&g_deg[v], 1);
                g_col[i - NE]  = v;
                g_rank[i - NE] = r;
            }
        }
        if (i < NN) {
            g_batchi[i] = f64 ? (int)((const long long*)batch)[i] : ((const int*)batch)[i];
        }
        return;
    }

    // ---- prep: split-K weight folds ----
    __shared__ float swl[HID];
    __shared__ float sred[4][HID];
    __shared__ float sred4[4][4][HID];
    __shared__ float sbn[HID], sbe[HID];
    const int c = t & 127;
    const int q = t >> 7;

    if (b < 56) {
        const float* Wl;
        const float* Wr;
        float* out;
        int orow;
        if (b < 48) {
            int grp = b >> 4;
            orow = b & 15;
            Wl = Wn + orow*HID;
            if      (grp == 0) { Wr = Wm;           out = g_WA;  }
            else if (grp == 1) { Wr = Wm + HID*HID; out = g_WB;  }
            else               { Wr = Wu;           out = g_WU1; }
        } else {
            orow = b - 48;
            Wl = We + orow*HID;
            Wr = Wm + 2*HID*HID;
            out = g_WE2;
        }
        if (t < HID) swl[t] = Wl[t];
        __syncthreads();
        float a0 = 0.f, a1 = 0.f;
        const int k0 = 32*q;
        #pragma unroll
        for (int kk = 0; kk < 32; kk += 2) {
            a0 += swl[k0+kk]   * Wr[(k0+kk)*HID + c];
            a1 += swl[k0+kk+1] * Wr[(k0+kk+1)*HID + c];
        }
        sred[q][c] = a0 + a1;
        __syncthreads();
        if (q == 0)
            out[orow*HID + c] = (sred[0][c] + sred[1][c]) + (sred[2][c] + sred[3][c]);
    } else {
        if (t < HID) { sbn[t] = bn[t]; sbe[t] = be[t]; }
        __syncthreads();
        float p0 = 0.f, p1 = 0.f, p2 = 0.f, p3 = 0.f;
        const int k0 = 32*q;
        #pragma unroll
        for (int kk = 0; kk < 32; kk++) {
            int k = k0 + kk;
            float bnk = sbn[k];
            p0 += bnk    * Wm[k*HID + c];
            p1 += bnk    * Wm[(HID + k)*HID + c];
            p2 += sbe[k] * Wm[(2*HID + k)*HID + c];
            p3 += bnk    * Wu[k*HID + c];
        }
        sred4[q][0][c] = p0; sred4[q][1][c] = p1;
        sred4[q][2][c] = p2; sred4[q][3][c] = p3;
        __syncthreads();
        if (q == 0) {
            float b0 = sred4[0][0][c]+sred4[1][0][c]+sred4[2][0][c]+sred4[3][0][c];
            float b1 = sred4[0][1][c]+sred4[1][1][c]+sred4[2][1][c]+sred4[3][1][c];
            float b2 = sred4[0][2][c]+sred4[1][2][c]+sred4[2][2][c]+sred4[3][2][c];
            float u0 = sred4[0][3][c]+sred4[1][3][c]+sred4[2][3][c]+sred4[3][3][c];
            g_bconst[c] = bm[c] + b0 + b1 + b2;
            g_bup[c]    = bu[c] + u0;
        }
    }
}

// ---------------- 2: fused exclusive scan (decoupled lookback), clears g_deg ----------------
__global__ __launch_bounds__(1024) void k_scan() {
    __shared__ int swsum[32];
    __shared__ int soff;
    int t = threadIdx.x, b = blockIdx.x;
    int idx = b * 1024 + t;
    int lane = t & 31, warp = t >> 5;
    int d = (idx < NN) ? g_deg[idx] : 0;
    if (idx < NN) g_deg[idx] = 0;            // consume-and-clear for next call

    int v = d;
    #pragma unroll
    for (int o = 1; o < 32; o <<= 1) {
        int u = __shfl_up_sync(0xffffffffu, v, o);
        if (lane >= o) v += u;
    }
    if (lane == 31) swsum[warp] = v;
    __syncthreads();
    if (warp == 0) {
        int s = swsum[lane];
        #pragma unroll
        for (int o = 1; o < 32; o <<= 1) {
            int u = __shfl_up_sync(0xffffffffu, s, o);
            if (lane >= o) s += u;
        }
        swsum[lane] = s;
    }
    __syncthreads();
    int incl = v + ((warp > 0) ? swsum[warp - 1] : 0);

    if (t == 1023) {                          // publish block total
        g_bsum[b] = incl;
        __threadfence();
        atomicExch(&g_sflag[b], 1);
    }
    if (t < 32) {                             // lookback over predecessors
        int acc = 0;
        for (int j = t; j < b; j += 32) {
            while (atomicAdd(&g_sflag[j], 0) == 0) {}
            acc += atomicAdd(&g_bsum[j], 0);
        }
        #pragma unroll
        for (int o = 16; o > 0; o >>= 1) acc += __shfl_down_sync(0xffffffffu, acc, o);
        if (t == 0) soff = acc;
    }
    __syncthreads();
    if (idx < NN) g_ptr[idx] = (incl - d) + soff;
    if (b == 0 && t == 0) g_ptr[NN] = NE;     // degree sum is NE by construction
}

// ---------------- 3: fused node projections (blocks 0..NBN-1) + scatter (rest) ----------------
__global__ __launch_bounds__(256) void k_scatternode(const float* __restrict__ x) {
    const int t = threadIdx.x;
    const int b = blockIdx.x;

    if (b >= NBN) {                    // ---- scatter (pure stores) + clear sflag ----
        int i = (b - NBN) * 256 + t;
        if (i < NE) {
            int c = g_col[i];
            g_epack[g_ptr[c] + g_rank[i]] = make_int2(g_row[i], i);
        }
        if (i < SBLK) g_sflag[i] = 0;  // consume-and-clear for next call
        return;
    }

    // ---- node: pa/pb via channel-per-thread, broadcast LDS, f32x2 ----
    __shared__ __align__(16) float sxT[16][36];   // [i][n], 144B rows
    const int n0 = b * 32;
    #pragma unroll
    for (int r = 0; r < 2; r++) {
        int f = t + 256*r;             // 512 elements = 32 nodes x 16 feats
        int n = f >> 4, i = f & 15;
        int node = n0 + n;
        sxT[i][n] = (node < NN) ? x[(long long)node*16 + i] : 0.f;
    }
    __syncthreads();

    const int ch  = t & 127;
    const float* W   = (t >= 128) ? g_WB : g_WA;
    float*       OUT = (t >= 128) ? g_pb : g_pa;

    unsigned long long acc2[16];
    #pragma unroll
    for (int p = 0; p < 16; p++) acc2[p] = 0ULL;

    #pragma unroll
    for (int i = 0; i < 16; i++) {
        unsigned long long w2 = splat2(W[i*HID + ch]);
        const ulonglong2* srow = (const ulonglong2*)&sxT[i][0];
        #pragma unroll
        for (int qq = 0; qq < 8; qq++) {
            ulonglong2 a = srow[qq];   // broadcast (all lanes same addr)
            fma_f32x2(acc2[2*qq],   a.x, w2);
            fma_f32x2(acc2[2*qq+1], a.y, w2);
        }
    }
    #pragma unroll
    for (int p = 0; p < 16; p++) {
        float v0, v1;
        unpack2(acc2[p], v0, v1);
        int na = n0 + 2*p, nb2 = n0 + 2*p + 1;
        if (na  < NN) OUT[(long long)na *HID + ch] = v0;   // coalesced across ch
        if (nb2 < NN) OUT[(long long)nb2*HID + ch] = v1;
    }
}

// ---------------- 4: FUSED agg + update — smem handoff, no g_agg round-trip ----------------
__global__ __launch_bounds__(128, 6) void k_aggupdate(const float* __restrict__ ea,
                                                      const float* __restrict__ x,
                                                      const float* __restrict__ Wu) {
    __shared__ float4 sbc[32];
    __shared__ __align__(16) float saggT[HID][UNB + 4];   // phase A writes, phase B reads
    __shared__ __align__(16) float sxT[16][UNB + 4];
    __shared__ int sbatch[UNB];

    const int t = threadIdx.x;
    const int warp = t >> 5, lane = t & 31;
    const int n0 = blockIdx.x * UNB;

    // ---- fills that phase A doesn't need: overlap their latency with weight loads ----
    if (t < UNB) {
        int node = n0 + t;
        sbatch[t] = (node < NN) ? g_batchi[node] : 0;
    }
    #pragma unroll
    for (int r = 0; r < 4; r++) {
        int f = t + 128*r;             // 512 = 32 nodes x 16 feats
        int n = f >> 4, i = f & 15;
        int node = n0 + n;
        sxT[i][n] = (node < NN) ? x[(long long)node*16 + i] : 0.f;
    }

    // ---- phase A: aggregation, result -> saggT directly ----
    unsigned long long wx[8], wy[8];   // WE2[j][4*lane..4*lane+3] per lane
    #pragma unroll
    for (int j = 0; j < 8; j++) {
        ulonglong2 w = ((const ulonglong2*)g_WE2)[j*32 + lane];
        wx[j] = w.x; wy[j] = w.y;
    }
    if (t < 32) sbc[t] = ((const float4*)g_bconst)[t];
    __syncthreads();

    const int ch4 = 4*lane;
    for (int s = 0; s < 8; s++) {
        int nloc = s*4 + warp;          // round-robin nodes over warps
        int node = n0 + nloc;
        if (node >= NN) {
            saggT[ch4+0][nloc] = 0.f;
            saggT[ch4+1][nloc] = 0.f;
            saggT[ch4+2][nloc] = 0.f;
            saggT[ch4+3][nloc] = 0.f;
            continue;
        }
        int beg = g_ptr[node];
        int end = g_ptr[node + 1];

        float4 pbv = ((const float4*)g_pb)[node*32 + lane];
        float4 bc  = sbc[lane];
        unsigned long long bx0 = pack2(pbv.x + bc.x, pbv.y + bc.y);
        unsigned long long bx1 = pack2(pbv.z + bc.z, pbv.w + bc.w);

        float4 acc = {0.f, 0.f, 0.f, 0.f};
        int2 e1 = {0,0}, e2 = {0,0};
        ulonglong2 pav = {0ULL, 0ULL};
        float4 A = {0,0,0,0}, B = {0,0,0,0};
        if (beg < end)     e1 = g_epack[beg];
        if (beg + 1 < end) e2 = g_epack[beg + 1];
        if (beg < end) {
            pav = ((const ulonglong2*)g_pa)[e1.x*32 + lane];
            const float4* eap = (const float4*)(ea + (long long)e1.y*8);
            A = eap[0]; B = eap[1];
        }
        for (int p = beg; p < end; p++) {
            ulonglong2 pc = pav;
            float4 Ac = A, Bc = B;
            e1 = e2;
            if (p + 2 < end) e2 = g_epack[p + 2];
            if (p + 1 < end) {
                pav = ((const ulonglong2*)g_pa)[e1.x*32 + lane];
                const float4* eap = (const float4*)(ea + (long long)e1.y*8);
                A = eap[0]; B = eap[1];
            }
            unsigned long long m0 = add_f32x2(pc.x, bx0);
            unsigned long long m1 = add_f32x2(pc.y, bx1);
            float ej[8] = {Ac.x, Ac.y, Ac.z, Ac.w, Bc.x, Bc.y, Bc.z, Bc.w};
            #pragma unroll
            for (int j = 0; j < 8; j++) {
                unsigned long long ej2 = splat2(ej[j]);
                fma_f32x2(m0, ej2, wx[j]);
                fma_f32x2(m1, ej2, wy[j]);
            }
            float f0, f1, f2, f3;
            unpack2(m0, f0, f1);
            unpack2(m1, f2, f3);
            acc.x += fmaxf(f0, 0.f);
            acc.y += fmaxf(f1, 0.f);
            acc.z += fmaxf(f2, 0.f);
            acc.w += fmaxf(f3, 0.f);
        }
        float inv = 1.f / fmaxf((float)(end - beg), 1.f);
        saggT[ch4+0][nloc] = acc.x * inv;
        saggT[ch4+1][nloc] = acc.y * inv;
        saggT[ch4+2][nloc] = acc.z * inv;
        saggT[ch4+3][nloc] = acc.w * inv;
    }
    __syncthreads();   // saggT + sxT + sbatch all visible

    // ---- phase B: update + pooling (reads saggT directly) ----
    const int c = t;
    unsigned long long acc2[UNB/2];
    #pragma unroll
    for (int p = 0; p < UNB/2; p++) acc2[p] = 0ULL;

    #pragma unroll
    for (int i = 0; i < 16; i++) {
        unsigned long long w2 = splat2(g_WU1[i*HID + c]);
        const ulonglong2* srow = (const ulonglong2*)&sxT[i][0];
        #pragma unroll
        for (int q = 0; q < UNB/4; q++) {
            ulonglong2 a = srow[q];
            fma_f32x2(acc2[2*q],   a.x, w2);
            fma_f32x2(acc2[2*q+1], a.y, w2);
        }
    }
    // Wu_bot loop with explicit 1-ahead weight prefetch
    {
        const float* wub = Wu + HID*HID + c;
        float wnext = wub[0];
        #pragma unroll 4
        for (int k = 0; k < HID; k++) {
            float wcur = wnext;
            if (k + 1 < HID) wnext = wub[(k + 1) * HID];
            unsigned long long w2 = splat2(wcur);
            const ulonglong2* srow = (const ulonglong2*)&saggT[k][0];
            #pragma unroll
            for (int q = 0; q < UNB/4; q++) {
                ulonglong2 a = srow[q];
                fma_f32x2(acc2[2*q],   a.x, w2);
                fma_f32x2(acc2[2*q+1], a.y, w2);
            }
        }
    }

    float bupv = g_bup[c];
    int   rep  = blockIdx.x & (REP - 1);
    float* gsbase = &g_gsum[rep*NGR*HID];
    int   cur = sbatch[0];
    float sum = 0.f;
    #pragma unroll
    for (int p = 0; p < UNB/2; p++) {
        float hv[2];
        unpack2(acc2[p], hv[0], hv[1]);
        #pragma unroll
        for (int q = 0; q < 2; q++) {
            int n = 2*p + q;
            int node = n0 + n;
            if (node < NN) {
                float h = fmaxf(hv[q] + bupv, 0.f);
                int b = sbatch[n];
                if (b != cur) {
                    red_f32(gsbase + cur*HID + c, sum);
                    cur = b; sum = 0.f;
                }
                sum += h;
            }
        }
    }
    red_f32(gsbase + cur*HID + c, sum);

    if (t < UNB) {
        int node = n0 + t;
        if (node < NN) red_f32(&g_gcnt[rep*NGR + sbatch[t]], 1.0f);
    }
}

// ---------------- 5: readout MLP, clears g_gsum/g_gcnt ----------------
__global__ __launch_bounds__(128) void k_final(const float* __restrict__ Wr1,
                                               const float* __restrict__ br1,
                                               const float* __restrict__ Wr2,
                                               const float* __restrict__ br2,
                                               float* __restrict__ out) {
    __shared__ float sg[HID];
    __shared__ float sred[4];
    int g = blockIdx.x, t = threadIdx.x;
    float s = 0.f;
    for (int r = 0; r < REP; r++) s += g_gsum[r*NGR*HID + g*HID + t];
    float gc = 0.f;
    for (int r = 0; r < REP; r++) gc += g_gcnt[r*NGR + g];
    sg[t] = s / fmaxf(gc, 1.f);
    __syncthreads();
    // consume-and-clear (this block owns graph g's slots)
    for (int r = 0; r < REP; r++) g_gsum[r*NGR*HID + g*HID + t] = 0.f;
    if (t == 0) for (int r = 0; r < REP; r++) g_gcnt[r*NGR + g] = 0.f;

    float acc = br1[t];
    for (int k = 0; k < HID; k++) acc += sg[k] * Wr1[k*HID + t];
    acc = fmaxf(acc, 0.f);
    float v = acc * Wr2[t];
    #pragma unroll
    for (int o = 16; o > 0; o >>= 1) v += __shfl_down_sync(0xffffffffu, v, o);
    if ((t & 31) == 0) sred[t >> 5] = v;
    __syncthreads();
    if (t == 0) out[g] = sred[0] + sred[1] + sred[2] + sred[3] + br2[0];
}

// ---------------- launch ----------------
extern "C" void kernel_launch(void* const* d_in, const int* in_sizes, int n_in,
                              void* d_out, int out_size) {
    const float* x     = (const float*)d_in[0];
    const float* ea    = (const float*)d_in[1];
    const void*  ei    = d_in[2];
    const void*  batch = d_in[3];
    const float* Wn  = (const float*)d_in[4];
    const float* bn  = (const float*)d_in[5];
    const float* We  = (const float*)d_in[6];
    const float* be  = (const float*)d_in[7];
    const float* Wm  = (const float*)d_in[8];
    const float* bm  = (const float*)d_in[9];
    const float* Wu  = (const float*)d_in[10];
    const float* bu  = (const float*)d_in[11];
    const float* Wr1 = (const float*)d_in[12];
    const float* br1 = (const float*)d_in[13];
    const float* Wr2 = (const float*)d_in[14];
    const float* br2 = (const float*)d_in[15];
    float* out = (float*)d_out;

    k_prepconvert <<<57 + NBC, 512>>>(ei, batch, Wn, bn, We, be, Wm, bm, Wu, bu);
    k_scan        <<<SBLK, 1024>>>();
    k_scatternode <<<NBN + NBS, 256>>>(x);
    k_aggupdate   <<<NBN, 128>>>(ea, x, Wu);     // launch #4 -> profiled
    k_final       <<<NGR, 128>>>(Wr1, br1, Wr2, br2, out);
}

// round 17
// speedup vs baseline: 1.6540x; 1.1380x over previous
#include <cuda_runtime.h>

#define NN   50000
#define NE   500000
#define HID  128
#define NGR  64
#define REP  32
#define UNB  32    // nodes per (agg+update) block
#define SBLK 49    // ceil(NN/1024) scan blocks
#define NBN  1563  // ceil(NN/32) node blocks
#define NBC  1954  // ceil(2*NE/512) convert blocks
#define NBS  1954  // ceil(NE/256) scatter blocks

// ---------------- device scratch (no allocations allowed) ----------------
// g_deg, g_sflag, g_gsum, g_gcnt start zero (static init) and are re-zeroed
// by their consumers each call, so every kernel_launch sees identical state.
__device__ __align__(16) float g_pa[NN*HID];        // x @ (Wn Wm_a)
__device__ __align__(16) float g_pb[NN*HID];        // x @ (Wn Wm_b)
__device__ __align__(16) float g_gsum[REP*NGR*HID]; // replicated graph sums
__device__ __align__(16) float g_gcnt[REP*NGR];
__device__ __align__(16) float g_WA[16*HID];        // Wn @ Wm_a
__device__ __align__(16) float g_WB[16*HID];        // Wn @ Wm_b
__device__ __align__(16) float g_WE2[8*HID];        // We @ Wm_c
__device__ __align__(16) float g_WU1[16*HID];       // Wn @ Wu_top
__device__ __align__(16) float g_bconst[HID];       // bn@Wm_a + bn@Wm_b + be@Wm_c + bm
__device__ __align__(16) float g_bup[HID];          // bn@Wu_top + bu
__device__ int  g_row[NE];
__device__ int  g_col[NE];
__device__ int  g_rank[NE];                         // within-destination rank
__device__ int2 g_epack[NE];                        // CSR payload: (src_row, edge_id)
__device__ int  g_deg[NN];
__device__ int  g_ptr[NN+1];
__device__ int  g_bsum[SBLK];
__device__ int  g_sflag[SBLK];
__device__ int  g_batchi[NN];

// ---------------- helpers ----------------
__device__ __forceinline__ void red_f32(float* p, float v) {
    asm volatile("red.global.add.f32 [%0], %1;" :: "l"(p), "f"(v) : "memory");
}
__device__ __forceinline__ unsigned long long splat2(float w) {
    unsigned long long r;
    asm("mov.b64 %0, {%1, %1};" : "=l"(r) : "r"(__float_as_uint(w)));
    return r;
}
__device__ __forceinline__ unsigned long long pack2(float a, float b) {
    unsigned long long r;
    asm("mov.b64 %0, {%1, %2};" : "=l"(r) : "r"(__float_as_uint(a)), "r"(__float_as_uint(b)));
    return r;
}
__device__ __forceinline__ void unpack2(unsigned long long v, float& a, float& b) {
    unsigned lo, hi;
    asm("mov.b64 {%0, %1}, %2;" : "=r"(lo), "=r"(hi) : "l"(v));
    a = __uint_as_float(lo); b = __uint_as_float(hi);
}
__device__ __forceinline__ void fma_f32x2(unsigned long long& d,
                                          unsigned long long a,
                                          unsigned long long b) {
    asm("fma.rn.f32x2 %0, %1, %2, %0;" : "+l"(d) : "l"(a), "l"(b));
}
__device__ __forceinline__ unsigned long long add_f32x2(unsigned long long a,
                                                        unsigned long long b) {
    unsigned long long r;
    asm("add.rn.f32x2 %0, %1, %2;" : "=l"(r) : "l"(a), "l"(b));
    return r;
}

// ---------------- 1: fused weight-fold (blocks 0..56) + convert (rest) ----------------
__global__ __launch_bounds__(512) void k_prepconvert(
        const void* __restrict__ ei, const void* __restrict__ batch,
        const float* __restrict__ Wn, const float* __restrict__ bn,
        const float* __restrict__ We, const float* __restrict__ be,
        const float* __restrict__ Wm, const float* __restrict__ bm,
        const float* __restrict__ Wu, const float* __restrict__ bu) {
    const int t = threadIdx.x;
    const int b = blockIdx.x;

    if (b >= 57) {                     // ---- convert: indices + histogram + rank ----
        int i = (b - 57) * 512 + t;
        const int* ei32 = (const int*)ei;
        bool active = (i < 2*NE);
        int j = (i < NE) ? i : i - NE;
        int hw = active ? ei32[2*j + 1] : 0;
        unsigned m = __ballot_sync(0xffffffffu, active && (hw != 0));
        const bool f64 = (m == 0u);    // int64: all odd words zero
        if (active) {
            int v = f64 ? (int)((const long long*)ei)[i] : ei32[i];
            if (i < NE) {
                g_row[i] = v;
            } else {
                int r = atomicAdd(&g_deg[v], 1);
                g_col[i - NE]  = v;
                g_rank[i - NE] = r;
            }
        }
        if (i < NN) {
            g_batchi[i] = f64 ? (int)((const long long*)batch)[i] : ((const int*)batch)[i];
        }
        return;
    }

    // ---- prep: split-K weight folds ----
    __shared__ float swl[HID];
    __shared__ float sred[4][HID];
    __shared__ float sred4[4][4][HID];
    __shared__ float sbn[HID], sbe[HID];
    const int c = t & 127;
    const int q = t >> 7;

    if (b < 56) {
        const float* Wl;
        const float* Wr;
        float* out;
        int orow;
        if (b < 48) {
            int grp = b >> 4;
            orow = b & 15;
            Wl = Wn + orow*HID;
            if      (grp == 0) { Wr = Wm;           out = g_WA;  }
            else if (grp == 1) { Wr = Wm + HID*HID; out = g_WB;  }
            else               { Wr = Wu;           out = g_WU1; }
        } else {
            orow = b - 48;
            Wl = We + orow*HID;
            Wr = Wm + 2*HID*HID;
            out = g_WE2;
        }
        if (t < HID) swl[t] = Wl[t];
        __syncthreads();
        float a0 = 0.f, a1 = 0.f;
        const int k0 = 32*q;
        #pragma unroll
        for (int kk = 0; kk < 32; kk += 2) {
            a0 += swl[k0+kk]   * Wr[(k0+kk)*HID + c];
            a1 += swl[k0+kk+1] * Wr[(k0+kk+1)*HID + c];
        }
        sred[q][c] = a0 + a1;
        __syncthreads();
        if (q == 0)
            out[orow*HID + c] = (sred[0][c] + sred[1][c]) + (sred[2][c] + sred[3][c]);
    } else {
        if (t < HID) { sbn[t] = bn[t]; sbe[t] = be[t]; }
        __syncthreads();
        float p0 = 0.f, p1 = 0.f, p2 = 0.f, p3 = 0.f;
        const int k0 = 32*q;
        #pragma unroll
        for (int kk = 0; kk < 32; kk++) {
            int k = k0 + kk;
            float bnk = sbn[k];
            p0 += bnk    * Wm[k*HID + c];
            p1 += bnk    * Wm[(HID + k)*HID + c];
            p2 += sbe[k] * Wm[(2*HID + k)*HID + c];
            p3 += bnk    * Wu[k*HID + c];
        }
        sred4[q][0][c] = p0; sred4[q][1][c] = p1;
        sred4[q][2][c] = p2; sred4[q][3][c] = p3;
        __syncthreads();
        if (q == 0) {
            float b0 = sred4[0][0][c]+sred4[1][0][c]+sred4[2][0][c]+sred4[3][0][c];
            float b1 = sred4[0][1][c]+sred4[1][1][c]+sred4[2][1][c]+sred4[3][1][c];
            float b2 = sred4[0][2][c]+sred4[1][2][c]+sred4[2][2][c]+sred4[3][2][c];
            float u0 = sred4[0][3][c]+sred4[1][3][c]+sred4[2][3][c]+sred4[3][3][c];
            g_bconst[c] = bm[c] + b0 + b1 + b2;
            g_bup[c]    = bu[c] + u0;
        }
    }
}

// ---------------- 2: fused exclusive scan (decoupled lookback), clears g_deg ----------------
__global__ __launch_bounds__(1024) void k_scan() {
    __shared__ int swsum[32];
    __shared__ int soff;
    int t = threadIdx.x, b = blockIdx.x;
    int idx = b * 1024 + t;
    int lane = t & 31, warp = t >> 5;
    int d = (idx < NN) ? g_deg[idx] : 0;
    if (idx < NN) g_deg[idx] = 0;            // consume-and-clear for next call

    int v = d;
    #pragma unroll
    for (int o = 1; o < 32; o <<= 1) {
        int u = __shfl_up_sync(0xffffffffu, v, o);
        if (lane >= o) v += u;
    }
    if (lane == 31) swsum[warp] = v;
    __syncthreads();
    if (warp == 0) {
        int s = swsum[lane];
        #pragma unroll
        for (int o = 1; o < 32; o <<= 1) {
            int u = __shfl_up_sync(0xffffffffu, s, o);
            if (lane >= o) s += u;
        }
        swsum[lane] = s;
    }
    __syncthreads();
    int incl = v + ((warp > 0) ? swsum[warp - 1] : 0);

    if (t == 1023) {                          // publish block total
        g_bsum[b] = incl;
        __threadfence();
        atomicExch(&g_sflag[b], 1);
    }
    if (t < 32) {                             // lookback over predecessors
        int acc = 0;
        for (int j = t; j < b; j += 32) {
            while (atomicAdd(&g_sflag[j], 0) == 0) {}
            acc += atomicAdd(&g_bsum[j], 0);
        }
        #pragma unroll
        for (int o = 16; o > 0; o >>= 1) acc += __shfl_down_sync(0xffffffffu, acc, o);
        if (t == 0) soff = acc;
    }
    __syncthreads();
    if (idx < NN) g_ptr[idx] = (incl - d) + soff;
    if (b == 0 && t == 0) g_ptr[NN] = NE;     // degree sum is NE by construction
}

// ---------------- 3: fused node projections (blocks 0..NBN-1) + scatter (rest) ----------------
__global__ __launch_bounds__(256) void k_scatternode(const float* __restrict__ x) {
    const int t = threadIdx.x;
    const int b = blockIdx.x;

    if (b >= NBN) {                    // ---- scatter (pure stores) + clear sflag ----
        int i = (b - NBN) * 256 + t;
        if (i < NE) {
            int c = g_col[i];
            g_epack[g_ptr[c] + g_rank[i]] = make_int2(g_row[i], i);
        }
        if (i < SBLK) g_sflag[i] = 0;  // consume-and-clear for next call
        return;
    }

    // ---- node: pa/pb via channel-per-thread, broadcast LDS, f32x2 ----
    __shared__ __align__(16) float sxT[16][36];   // [i][n], 144B rows
    const int n0 = b * 32;
    #pragma unroll
    for (int r = 0; r < 2; r++) {
        int f = t + 256*r;             // 512 elements = 32 nodes x 16 feats
        int n = f >> 4, i = f & 15;
        int node = n0 + n;
        sxT[i][n] = (node < NN) ? x[(long long)node*16 + i] : 0.f;
    }
    __syncthreads();

    const int ch  = t & 127;
    const float* W   = (t >= 128) ? g_WB : g_WA;
    float*       OUT = (t >= 128) ? g_pb : g_pa;

    unsigned long long acc2[16];
    #pragma unroll
    for (int p = 0; p < 16; p++) acc2[p] = 0ULL;

    #pragma unroll
    for (int i = 0; i < 16; i++) {
        unsigned long long w2 = splat2(W[i*HID + ch]);
        const ulonglong2* srow = (const ulonglong2*)&sxT[i][0];
        #pragma unroll
        for (int qq = 0; qq < 8; qq++) {
            ulonglong2 a = srow[qq];   // broadcast (all lanes same addr)
            fma_f32x2(acc2[2*qq],   a.x, w2);
            fma_f32x2(acc2[2*qq+1], a.y, w2);
        }
    }
    #pragma unroll
    for (int p = 0; p < 16; p++) {
        float v0, v1;
        unpack2(acc2[p], v0, v1);
        int na = n0 + 2*p, nb2 = n0 + 2*p + 1;
        if (na  < NN) OUT[(long long)na *HID + ch] = v0;   // coalesced across ch
        if (nb2 < NN) OUT[(long long)nb2*HID + ch] = v1;
    }
}

// ---------------- 4: FUSED agg + update — smem handoff; phase B 4ch x 8n tiling ----------------
__global__ __launch_bounds__(128, 6) void k_aggupdate(const float* __restrict__ ea,
                                                      const float* __restrict__ x,
                                                      const float* __restrict__ Wu) {
    __shared__ float4 sbc[32];
    __shared__ __align__(16) float saggT[HID][UNB + 4];   // phase A writes, phase B reads
    __shared__ __align__(16) float sxT[16][UNB + 4];
    __shared__ int sbatch[UNB];

    const int t = threadIdx.x;
    const int warp = t >> 5, lane = t & 31;
    const int n0 = blockIdx.x * UNB;

    // ---- fills that phase A doesn't need: overlap their latency with weight loads ----
    if (t < UNB) {
        int node = n0 + t;
        sbatch[t] = (node < NN) ? g_batchi[node] : 0;
    }
    #pragma unroll
    for (int r = 0; r < 4; r++) {
        int f = t + 128*r;             // 512 = 32 nodes x 16 feats
        int n = f >> 4, i = f & 15;
        int node = n0 + n;
        sxT[i][n] = (node < NN) ? x[(long long)node*16 + i] : 0.f;
    }

    // ---- phase A: aggregation, result -> saggT directly ----
    unsigned long long wx[8], wy[8];   // WE2[j][4*lane..4*lane+3] per lane
    #pragma unroll
    for (int j = 0; j < 8; j++) {
        ulonglong2 w = ((const ulonglong2*)g_WE2)[j*32 + lane];
        wx[j] = w.x; wy[j] = w.y;
    }
    if (t < 32) sbc[t] = ((const float4*)g_bconst)[t];
    __syncthreads();

    const int ch4a = 4*lane;
    for (int s = 0; s < 8; s++) {
        int nloc = s*4 + warp;          // round-robin nodes over warps
        int node = n0 + nloc;
        if (node >= NN) {
            saggT[ch4a+0][nloc] = 0.f;
            saggT[ch4a+1][nloc] = 0.f;
            saggT[ch4a+2][nloc] = 0.f;
            saggT[ch4a+3][nloc] = 0.f;
            continue;
        }
        int beg = g_ptr[node];
        int end = g_ptr[node + 1];

        float4 pbv = ((const float4*)g_pb)[node*32 + lane];
        float4 bc  = sbc[lane];
        unsigned long long bx0 = pack2(pbv.x + bc.x, pbv.y + bc.y);
        unsigned long long bx1 = pack2(pbv.z + bc.z, pbv.w + bc.w);

        float4 acc = {0.f, 0.f, 0.f, 0.f};
        int2 e1 = {0,0}, e2 = {0,0};
        ulonglong2 pav = {0ULL, 0ULL};
        float4 A = {0,0,0,0}, B = {0,0,0,0};
        if (beg < end)     e1 = g_epack[beg];
        if (beg + 1 < end) e2 = g_epack[beg + 1];
        if (beg < end) {
            pav = ((const ulonglong2*)g_pa)[e1.x*32 + lane];
            const float4* eap = (const float4*)(ea + (long long)e1.y*8);
            A = eap[0]; B = eap[1];
        }
        for (int p = beg; p < end; p++) {
            ulonglong2 pc = pav;
            float4 Ac = A, Bc = B;
            e1 = e2;
            if (p + 2 < end) e2 = g_epack[p + 2];
            if (p + 1 < end) {
                pav = ((const ulonglong2*)g_pa)[e1.x*32 + lane];
                const float4* eap = (const float4*)(ea + (long long)e1.y*8);
                A = eap[0]; B = eap[1];
            }
            unsigned long long m0 = add_f32x2(pc.x, bx0);
            unsigned long long m1 = add_f32x2(pc.y, bx1);
            float ej[8] = {Ac.x, Ac.y, Ac.z, Ac.w, Bc.x, Bc.y, Bc.z, Bc.w};
            #pragma unroll
            for (int j = 0; j < 8; j++) {
                unsigned long long ej2 = splat2(ej[j]);
                fma_f32x2(m0, ej2, wx[j]);
                fma_f32x2(m1, ej2, wy[j]);
            }
            float f0, f1, f2, f3;
            unpack2(m0, f0, f1);
            unpack2(m1, f2, f3);
            acc.x += fmaxf(f0, 0.f);
            acc.y += fmaxf(f1, 0.f);
            acc.z += fmaxf(f2, 0.f);
            acc.w += fmaxf(f3, 0.f);
        }
        float inv = 1.f / fmaxf((float)(end - beg), 1.f);
        saggT[ch4a+0][nloc] = acc.x * inv;
        saggT[ch4a+1][nloc] = acc.y * inv;
        saggT[ch4a+2][nloc] = acc.z * inv;
        saggT[ch4a+3][nloc] = acc.w * inv;
    }
    __syncthreads();   // saggT + sxT + sbatch all visible

    // ---- phase B: thread = 4 channels (c4..c4+3) x 8 nodes (ng..ng+7, warp-uniform) ----
    const int c4 = 4 * lane;           // channel base
    const int ng = warp * 8;           // local node base (warp-uniform -> broadcast LDS)

    unsigned long long acc2[4][4];     // [ch][node-pair]
    #pragma unroll
    for (int chi = 0; chi < 4; chi++)
        #pragma unroll
        for (int np = 0; np < 4; np++) acc2[chi][np] = 0ULL;

    #pragma unroll
    for (int i = 0; i < 16; i++) {
        float4 w = ((const float4*)(g_WU1 + i*HID))[lane];
        const ulonglong2* arow = (const ulonglong2*)&sxT[i][ng];
        ulonglong2 a01 = arow[0];      // nodes ng..ng+3 (2 pairs)
        ulonglong2 a23 = arow[1];      // nodes ng+4..ng+7
        unsigned long long w0 = splat2(w.x), w1 = splat2(w.y);
        unsigned long long w2s = splat2(w.z), w3 = splat2(w.w);
        fma_f32x2(acc2[0][0], a01.x, w0); fma_f32x2(acc2[0][1], a01.y, w0);
        fma_f32x2(acc2[0][2], a23.x, w0); fma_f32x2(acc2[0][3], a23.y, w0);
        fma_f32x2(acc2[1][0], a01.x, w1); fma_f32x2(acc2[1][1], a01.y, w1);
        fma_f32x2(acc2[1][2], a23.x, w1); fma_f32x2(acc2[1][3], a23.y, w1);
        fma_f32x2(acc2[2][0], a01.x, w2s); fma_f32x2(acc2[2][1], a01.y, w2s);
        fma_f32x2(acc2[2][2], a23.x, w2s); fma_f32x2(acc2[2][3], a23.y, w2s);
        fma_f32x2(acc2[3][0], a01.x, w3); fma_f32x2(acc2[3][1], a01.y, w3);
        fma_f32x2(acc2[3][2], a23.x, w3); fma_f32x2(acc2[3][3], a23.y, w3);
    }
    // Wu_bot loop, coalesced float4 weight loads with 1-ahead prefetch
    {
        const float4* wub = (const float4*)(Wu + HID*HID) + lane;
        float4 wn = wub[0];
        #pragma unroll 4
        for (int k = 0; k < HID; k++) {
            float4 w = wn;
            if (k + 1 < HID) wn = wub[(k + 1) * (HID/4)];
            const ulonglong2* arow = (const ulonglong2*)&saggT[k][ng];
            ulonglong2 a01 = arow[0];
            ulonglong2 a23 = arow[1];
            unsigned long long w0 = splat2(w.x), w1 = splat2(w.y);
            unsigned long long w2s = splat2(w.z), w3 = splat2(w.w);
            fma_f32x2(acc2[0][0], a01.x, w0); fma_f32x2(acc2[0][1], a01.y, w0);
            fma_f32x2(acc2[0][2], a23.x, w0); fma_f32x2(acc2[0][3], a23.y, w0);
            fma_f32x2(acc2[1][0], a01.x, w1); fma_f32x2(acc2[1][1], a01.y, w1);
            fma_f32x2(acc2[1][2], a23.x, w1); fma_f32x2(acc2[1][3], a23.y, w1);
            fma_f32x2(acc2[2][0], a01.x, w2s); fma_f32x2(acc2[2][1], a01.y, w2s);
            fma_f32x2(acc2[2][2], a23.x, w2s); fma_f32x2(acc2[2][3], a23.y, w2s);
            fma_f32x2(acc2[3][0], a01.x, w3); fma_f32x2(acc2[3][1], a01.y, w3);
            fma_f32x2(acc2[3][2], a23.x, w3); fma_f32x2(acc2[3][3], a23.y, w3);
        }
    }

    // ---- pooling: 4 channels per thread over its 8 nodes ----
    float4 bup4 = ((const float4*)g_bup)[lane];
    float bup[4] = {bup4.x, bup4.y, bup4.z, bup4.w};
    int   rep  = blockIdx.x & (REP - 1);
    float* gsbase = &g_gsum[rep*NGR*HID];
    int   cur = sbatch[ng];
    float srun[4] = {0.f, 0.f, 0.f, 0.f};
    #pragma unroll
    for (int np = 0; np < 4; np++) {
        float hv[4][2];
        #pragma unroll
        for (int chi = 0; chi < 4; chi++)
            unpack2(acc2[chi][np], hv[chi][0], hv[chi][1]);
        #pragma unroll
        for (int q = 0; q < 2; q++) {
            int n = ng + 2*np + q;
            int node = n0 + n;
            if (node < NN) {
                int b = sbatch[n];
                if (b != cur) {
                    #pragma unroll
                    for (int chi = 0; chi < 4; chi++) {
                        red_f32(gsbase + cur*HID + c4 + chi, srun[chi]);
                        srun[chi] = 0.f;
                    }
                    cur = b;
                }
                #pragma unroll
                for (int chi = 0; chi < 4; chi++)
                    srun[chi] += fmaxf(hv[chi][q] + bup[chi], 0.f);
            }
        }
    }
    #pragma unroll
    for (int chi = 0; chi < 4; chi++)
        red_f32(gsbase + cur*HID + c4 + chi, srun[chi]);

    if (t < UNB) {
        int node = n0 + t;
        if (node < NN) red_f32(&g_gcnt[rep*NGR + sbatch[t]], 1.0f);
    }
}

// ---------------- 5: readout MLP, clears g_gsum/g_gcnt ----------------
__global__ __launch_bounds__(128) void k_final(const float* __restrict__ Wr1,
                                               const float* __restrict__ br1,
                                               const float* __restrict__ Wr2,
                                               const float* __restrict__ br2,
                                               float* __restrict__ out) {
    __shared__ float sg[HID];
    __shared__ float sred[4];
    int g = blockIdx.x, t = threadIdx.x;
    float s = 0.f;
    for (int r = 0; r < REP; r++) s += g_gsum[r*NGR*HID + g*HID + t];
    float gc = 0.f;
    for (int r = 0; r < REP; r++) gc += g_gcnt[r*NGR + g];
    sg[t] = s / fmaxf(gc, 1.f);
    __syncthreads();
    // consume-and-clear (this block owns graph g's slots)
    for (int r = 0; r < REP; r++) g_gsum[r*NGR*HID + g*HID + t] = 0.f;
    if (t == 0) for (int r = 0; r < REP; r++) g_gcnt[r*NGR + g] = 0.f;

    float acc = br1[t];
    for (int k = 0; k < HID; k++) acc += sg[k] * Wr1[k*HID + t];
    acc = fmaxf(acc, 0.f);
    float v = acc * Wr2[t];
    #pragma unroll
    for (int o = 16; o > 0; o >>= 1) v += __shfl_down_sync(0xffffffffu, v, o);
    if ((t & 31) == 0) sred[t >> 5] = v;
    __syncthreads();
    if (t == 0) out[g] = sred[0] + sred[1] + sred[2] + sred[3] + br2[0];
}

// ---------------- launch ----------------
extern "C" void kernel_launch(void* const* d_in, const int* in_sizes, int n_in,
                              void* d_out, int out_size) {
    const float* x     = (const float*)d_in[0];
    const float* ea    = (const float*)d_in[1];
    const void*  ei    = d_in[2];
    const void*  batch = d_in[3];
    const float* Wn  = (const float*)d_in[4];
    const float* bn  = (const float*)d_in[5];
    const float* We  = (const float*)d_in[6];
    const float* be  = (const float*)d_in[7];
    const float* Wm  = (const float*)d_in[8];
    const float* bm  = (const float*)d_in[9];
    const float* Wu  = (const float*)d_in[10];
    const float* bu  = (const float*)d_in[11];
    const float* Wr1 = (const float*)d_in[12];
    const float* br1 = (const float*)d_in[13];
    const float* Wr2 = (const float*)d_in[14];
    const float* br2 = (const float*)d_in[15];
    float* out = (float*)d_out;

    k_prepconvert <<<57 + NBC, 512>>>(ei, batch, Wn, bn, We, be, Wm, bm, Wu, bu);
    k_scan        <<<SBLK, 1024>>>();
    k_scatternode <<<NBN + NBS, 256>>>(x);
    k_aggupdate   <<<NBN, 128>>>(ea, x, Wu);     // launch #4 -> profiled
    k_final       <<<NGR, 128>>>(Wr1, br1, Wr2, br2, out);
}